// round 1
// baseline (speedup 1.0000x reference)
#include <cuda_runtime.h>
#include <cuda_bf16.h>
#include <math.h>

#define BATCH 4096
#define NDIM  64
#define HID   512
#define GB    8     // batch items per forward block

// ---------------- global scratch (device globals: no allocation allowed) ----
__device__ float g_G0[HID * NDIM];              // G0 = W_h[0] @ W_in
__device__ float g_maskB[3 * BATCH * HID];      // zero-branch delta masks (0/1)

// ---------------- prep: G0[i,d] = sum_j Wh0[i,j] * Win[j,d] ----------------
__global__ void prep_g0(const float* __restrict__ Wh, const float* __restrict__ Win) {
    int i = blockIdx.x;     // 0..511
    int d = threadIdx.x;    // 0..63
    float acc = 0.f;
    for (int j = 0; j < HID; j++)
        acc += Wh[i * HID + j] * Win[j * NDIM + d];
    g_G0[i * NDIM + d] = acc;
}

// ---------------- forward both branches + masks + JVP ----------------------
// block: 512 threads (t = hidden index), GB batch items
__global__ __launch_bounds__(512) void fwd_kernel(
    const float* __restrict__ x,
    const float* __restrict__ Win, const float* __restrict__ bin,
    const float* __restrict__ Wh,  const float* __restrict__ bh,
    const float* __restrict__ Wout, const float* __restrict__ bout,
    float* __restrict__ out)
{
    extern __shared__ float sm[];
    float* sxA = sm;                 // GB*64  (xt)
    float* sxZ = sxA + GB * NDIM;    // GB*64  (x_zero)
    float* sxD = sxZ + GB * NDIM;    // GB*64  (xtdot)
    float* shA = sxD + GB * NDIM;    // GB*512 main-branch activations
    float* shB = shA + GB * HID;     // GB*512 zero-branch activations
    float* sv  = shB + GB * HID;     // GB*512 JVP vector

    int t  = threadIdx.x;
    int b0 = blockIdx.x * GB;

    // load x slices
    for (int i = t; i < GB * 192; i += 512) {
        int g = i / 192, c = i % 192;
        float v = x[(b0 + g) * 192 + c];
        if (c < 64)       sxA[g * NDIM + c] = v;
        else if (c < 128) sxD[g * NDIM + (c - 64)] = v;
        else              sxZ[g * NDIM + (c - 128)] = v;
    }
    __syncthreads();

    // h0 (no relu) for both branches + v0 = G0 @ xtdot
    {
        float aA[GB], aB[GB], aV[GB];
        float bi = bin[t];
#pragma unroll
        for (int g = 0; g < GB; g++) { aA[g] = bi; aB[g] = bi; aV[g] = 0.f; }
        for (int d = 0; d < NDIM; d++) {
            float w  = Win[t * NDIM + d];
            float g0 = g_G0[t * NDIM + d];
#pragma unroll
            for (int g = 0; g < GB; g++) {
                aA[g] += w  * sxA[g * NDIM + d];
                aB[g] += w  * sxZ[g * NDIM + d];
                aV[g] += g0 * sxD[g * NDIM + d];
            }
        }
#pragma unroll
        for (int g = 0; g < GB; g++) {
            shA[g * HID + t] = aA[g];
            shB[g * HID + t] = aB[g];
            sv [g * HID + t] = aV[g];
        }
    }
    __syncthreads();

#pragma unroll
    for (int l = 0; l < 3; l++) {
        const float* W = Wh + (size_t)l * HID * HID;
        const float4* Wr = (const float4*)(W + t * HID);
        float bias = bh[l * HID + t];

        // ---- pass 1: h_{l+1} = relu(W h_l + b); v = W v (layers 1,2) ----
        float aA[GB], aB[GB], aV[GB];
#pragma unroll
        for (int g = 0; g < GB; g++) { aA[g] = bias; aB[g] = bias; aV[g] = 0.f; }
#pragma unroll 4
        for (int k4 = 0; k4 < HID / 4; k4++) {
            float4 w4 = Wr[k4];
            int k = k4 * 4;
#pragma unroll
            for (int q = 0; q < 4; q++) {
                float w = (&w4.x)[q];
#pragma unroll
                for (int g = 0; g < GB; g++) {
                    aA[g] += w * shA[g * HID + k + q];
                    aB[g] += w * shB[g * HID + k + q];
                    if (l > 0) aV[g] += w * sv[g * HID + k + q];
                }
            }
        }
        __syncthreads();   // all reads done before overwriting
#pragma unroll
        for (int g = 0; g < GB; g++) {
            shA[g * HID + t] = fmaxf(aA[g], 0.f);
            shB[g * HID + t] = fmaxf(aB[g], 0.f);
            if (l > 0) sv[g * HID + t] = aV[g];
        }
        __syncthreads();

        // ---- pass 2: delta^{(l)} = (W h_{l+1} + b > 0)  (the "bug-faithful" mask)
#pragma unroll
        for (int g = 0; g < GB; g++) { aA[g] = bias; aB[g] = bias; }
#pragma unroll 4
        for (int k4 = 0; k4 < HID / 4; k4++) {
            float4 w4 = Wr[k4];
            int k = k4 * 4;
#pragma unroll
            for (int q = 0; q < 4; q++) {
                float w = (&w4.x)[q];
#pragma unroll
                for (int g = 0; g < GB; g++) {
                    aA[g] += w * shA[g * HID + k + q];
                    aB[g] += w * shB[g * HID + k + q];
                }
            }
        }
#pragma unroll
        for (int g = 0; g < GB; g++) {
            float dA = aA[g] > 0.f ? 1.f : 0.f;
            float dB = aB[g] > 0.f ? 1.f : 0.f;
            sv[g * HID + t] *= dA;                         // mask JVP vector
            g_maskB[((size_t)l * BATCH + (b0 + g)) * HID + t] = dB;
        }
        __syncthreads();
    }

    // ---- final: h_out = Wout h3 + bout ; h_dot = Wout v -------------------
    {
        int n = t >> 3, s = t & 7;   // 64 n-groups x 8 slices of K
        float aO[GB], aV[GB];
#pragma unroll
        for (int g = 0; g < GB; g++) { aO[g] = 0.f; aV[g] = 0.f; }
        for (int h = s * 64; h < s * 64 + 64; h++) {
            float w = Wout[n * HID + h];
#pragma unroll
            for (int g = 0; g < GB; g++) {
                aO[g] += w * shA[g * HID + h];
                aV[g] += w * sv [g * HID + h];
            }
        }
        float* red = shB;   // reuse (GB*512 floats = GB*64*8)
        // round 1: h_out
#pragma unroll
        for (int g = 0; g < GB; g++) red[(g * 64 + n) * 8 + s] = aO[g];
        __syncthreads();
        if (s == 0) {
#pragma unroll
            for (int g = 0; g < GB; g++) {
                float sum = bout[n];
                for (int ss = 0; ss < 8; ss++) sum += red[(g * 64 + n) * 8 + ss];
                out[(size_t)(b0 + g) * 192 + n] = sum;
            }
        }
        __syncthreads();
        // round 2: h_dot
#pragma unroll
        for (int g = 0; g < GB; g++) red[(g * 64 + n) * 8 + s] = aV[g];
        __syncthreads();
        if (s == 0) {
#pragma unroll
            for (int g = 0; g < GB; g++) {
                float sum = 0.f;
                for (int ss = 0; ss < 8; ss++) sum += red[(g * 64 + n) * 8 + ss];
                out[(size_t)(b0 + g) * 192 + 64 + n] = sum;
            }
        }
    }
}

// ---------------- Jacobian chain kernel ------------------------------------
// one block per batch item, 256 threads.
// O[n,k] = mask[k] * sum_h A[n,h] * W[h,k]   (A,O bf16 in SMEM, W fp32 global)
__device__ __forceinline__ void gemm_step(
    const __nv_bfloat16* __restrict__ A, const float* __restrict__ W,
    __nv_bfloat16* __restrict__ O, const float* __restrict__ mask,
    __nv_bfloat16* __restrict__ sW, int t)
{
    int tn = t >> 4, tk = t & 15;    // 16 x 16 thread grid
    for (int k0 = 0; k0 < HID; k0 += 128) {
        float acc[4][8];
#pragma unroll
        for (int i = 0; i < 4; i++)
#pragma unroll
            for (int j = 0; j < 8; j++) acc[i][j] = 0.f;

        for (int h0 = 0; h0 < HID; h0 += 64) {
            __syncthreads();  // protect sW reuse
            // load W[h0:h0+64, k0:k0+128] -> sW (bf16), coalesced float4
#pragma unroll
            for (int r = 0; r < 8; r++) {
                int flat = t + 256 * r;        // 0..2047 float4 units
                int row = flat >> 5, c4 = flat & 31;
                float4 w4 = *(const float4*)(W + (size_t)(h0 + row) * HID + k0 + c4 * 4);
                __nv_bfloat16* dst = &sW[row * 128 + c4 * 4];
                dst[0] = __float2bfloat16(w4.x); dst[1] = __float2bfloat16(w4.y);
                dst[2] = __float2bfloat16(w4.z); dst[3] = __float2bfloat16(w4.w);
            }
            __syncthreads();
#pragma unroll 2
            for (int hh = 0; hh < 64; hh++) {
                float a[4];
#pragma unroll
                for (int i = 0; i < 4; i++)
                    a[i] = __bfloat162float(A[(tn * 4 + i) * HID + h0 + hh]);
                const __nv_bfloat162* bp = (const __nv_bfloat162*)&sW[hh * 128 + tk * 8];
                float2 b01 = __bfloat1622float2(bp[0]);
                float2 b23 = __bfloat1622float2(bp[1]);
                float2 b45 = __bfloat1622float2(bp[2]);
                float2 b67 = __bfloat1622float2(bp[3]);
                float bb[8] = {b01.x, b01.y, b23.x, b23.y, b45.x, b45.y, b67.x, b67.y};
#pragma unroll
                for (int i = 0; i < 4; i++)
#pragma unroll
                    for (int j = 0; j < 8; j++) acc[i][j] += a[i] * bb[j];
            }
        }
        // write masked bf16 output (each thread owns its tile -> no race)
#pragma unroll
        for (int i = 0; i < 4; i++) {
            int n = tn * 4 + i;
#pragma unroll
            for (int j = 0; j < 8; j++) {
                int k = k0 + tk * 8 + j;
                O[n * HID + k] = __float2bfloat16(acc[i][j] * mask[k]);
            }
        }
    }
    __syncthreads();
}

__global__ __launch_bounds__(256) void z_kernel(
    const float* __restrict__ Wh, const float* __restrict__ Wout,
    float* __restrict__ out)
{
    extern __shared__ char smc[];
    __nv_bfloat16* sA  = (__nv_bfloat16*)smc;        // 64*512 bf16
    __nv_bfloat16* sU  = sA + 64 * HID;              // 64*512 bf16
    __nv_bfloat16* sW  = sU + 64 * HID;              // 64*128 bf16 chunk
    float* sm1 = (float*)(sW + 64 * 128);            // delta1
    float* sm2 = sm1 + HID;                          // delta2
    float* sm3 = sm2 + HID;                          // delta3
    float* red = sm3 + HID;                          // 64*16

    int b = blockIdx.x;
    int t = threadIdx.x;

    for (int i = t; i < HID; i += 256) {
        sm1[i] = g_maskB[((size_t)0 * BATCH + b) * HID + i];
        sm2[i] = g_maskB[((size_t)1 * BATCH + b) * HID + i];
        sm3[i] = g_maskB[((size_t)2 * BATCH + b) * HID + i];
    }
    __syncthreads();

    // A0 = Wout ∘ delta3   (64 x 512)
    for (int i = t; i < 64 * HID; i += 256) {
        int h = i & (HID - 1);
        sA[i] = __float2bfloat16(Wout[i] * sm3[h]);
    }
    __syncthreads();

    // U2 = (A0 @ Wh2) ∘ delta2 ;  U3 = (U2 @ Wh1) ∘ delta1
    gemm_step(sA, Wh + (size_t)2 * HID * HID, sU, sm2, sW, t);
    gemm_step(sU, Wh + (size_t)1 * HID * HID, sA, sm1, sW, t);

    // J = U3 @ G0 (64 x 64), then zng = row norms
    {
        int tn = t >> 4, td = t & 15;    // n-tile 4, d-tile 4
        float acc[4][4];
#pragma unroll
        for (int i = 0; i < 4; i++)
#pragma unroll
            for (int j = 0; j < 4; j++) acc[i][j] = 0.f;

        for (int j0 = 0; j0 < HID; j0 += 64) {
            __syncthreads();
#pragma unroll
            for (int r = 0; r < 4; r++) {
                int flat = t + 256 * r;       // 0..1023 float4 units
                int row = flat >> 4, c4 = flat & 15;
                float4 w4 = *(const float4*)(g_G0 + (size_t)(j0 + row) * NDIM + c4 * 4);
                __nv_bfloat16* dst = &sW[row * 64 + c4 * 4];
                dst[0] = __float2bfloat16(w4.x); dst[1] = __float2bfloat16(w4.y);
                dst[2] = __float2bfloat16(w4.z); dst[3] = __float2bfloat16(w4.w);
            }
            __syncthreads();
#pragma unroll 2
            for (int jj = 0; jj < 64; jj++) {
                float a[4];
#pragma unroll
                for (int i = 0; i < 4; i++)
                    a[i] = __bfloat162float(sA[(tn * 4 + i) * HID + j0 + jj]);
                const __nv_bfloat162* bp = (const __nv_bfloat162*)&sW[jj * 64 + td * 4];
                float2 b01 = __bfloat1622float2(bp[0]);
                float2 b23 = __bfloat1622float2(bp[1]);
                float bb[4] = {b01.x, b01.y, b23.x, b23.y};
#pragma unroll
                for (int i = 0; i < 4; i++)
#pragma unroll
                    for (int j = 0; j < 4; j++) acc[i][j] += a[i] * bb[j];
            }
        }
        // partial sum of squares over this thread's 4 d-values
#pragma unroll
        for (int i = 0; i < 4; i++) {
            float s = 0.f;
#pragma unroll
            for (int j = 0; j < 4; j++) s += acc[i][j] * acc[i][j];
            red[(tn * 4 + i) * 16 + td] = s;
        }
        __syncthreads();
        if (t < 64) {
            float s = 0.f;
#pragma unroll
            for (int k = 0; k < 16; k++) s += red[t * 16 + k];
            out[(size_t)b * 192 + 128 + t] = sqrtf(s);
        }
    }
}

// ---------------- launch ----------------------------------------------------
extern "C" void kernel_launch(void* const* d_in, const int* in_sizes, int n_in,
                              void* d_out, int out_size)
{
    const float* x    = (const float*)d_in[0];
    const float* Win  = (const float*)d_in[1];
    const float* bin  = (const float*)d_in[2];
    const float* Wh   = (const float*)d_in[3];
    const float* bh   = (const float*)d_in[4];
    const float* Wout = (const float*)d_in[5];
    const float* bout = (const float*)d_in[6];
    float* out = (float*)d_out;

    int B = in_sizes[0] / 192;   // 4096

    const int fwd_smem = (GB * (3 * NDIM + 3 * HID)) * sizeof(float);          // ~55 KB
    const int z_smem   = 2 * 64 * HID * 2 + 64 * 128 * 2                        // sA,sU,sW
                       + 3 * HID * 4 + 64 * 16 * 4;                             // masks + red
    cudaFuncSetAttribute(fwd_kernel, cudaFuncAttributeMaxDynamicSharedMemorySize, fwd_smem);
    cudaFuncSetAttribute(z_kernel,   cudaFuncAttributeMaxDynamicSharedMemorySize, z_smem);

    prep_g0<<<HID, NDIM>>>(Wh, Win);
    fwd_kernel<<<B / GB, 512, fwd_smem>>>(x, Win, bin, Wh, bh, Wout, bout, out);
    z_kernel<<<B, 256, z_smem>>>(Wh, Wout, out);
}

// round 3
// speedup vs baseline: 3.8625x; 3.8625x over previous
#include <cuda_runtime.h>
#include <cuda_bf16.h>
#include <math.h>
#include <stdint.h>

#define BATCH 4096
#define NDIM  64
#define HID   512
#define GB    8

// ---------------- device globals (static: allocation APIs are banned) -------
__device__ float g_G0[HID * NDIM];                          // G0 = Wh0 @ Win (fp32)
__device__ float g_maskB[3 * BATCH * HID];                  // zero-branch masks
__device__ __align__(16) __nv_bfloat16 g_WT[2][HID * HID];  // Wh1^T, Wh2^T  [n][k]
__device__ __align__(16) __nv_bfloat16 g_G0T[NDIM * HID];   // G0^T [d][h]
__device__ __align__(16) __nv_bfloat16 g_U[(size_t)(BATCH / 2) * 128 * HID]; // U staging

// ---------------- SMEM map for z_kernel (bytes) -----------------------------
#define ZP_MSK   0                       // 6*512 fp32 = 12288
#define ZP_A     12288                   // 128 rows * 520 bf16 = 133120
#define ZP_B     145408                  // 2 * (128 * 144B) = 36864
#define Z_SMEM   182272
#define A_STRIDE 1040                    // bytes per A row (520 bf16)
#define B_STRIDE 144                     // bytes per B row (72 bf16)

// ---------------- asm helpers ------------------------------------------------
__device__ __forceinline__ uint32_t smem_u32(const void* p) {
    uint32_t a;
    asm("{ .reg .u64 t; cvta.to.shared.u64 t, %1; cvt.u32.u64 %0, t; }" : "=r"(a) : "l"(p));
    return a;
}
#define CP16(dst, src)  asm volatile("cp.async.cg.shared.global [%0], [%1], 16;" :: "r"(dst), "l"(src))
#define CP_COMMIT()     asm volatile("cp.async.commit_group;" ::: "memory")
#define CP_WAIT(n)      asm volatile("cp.async.wait_group %0;" :: "n"(n) : "memory")

__device__ __forceinline__ void ldsm4(uint32_t addr, uint32_t& r0, uint32_t& r1,
                                      uint32_t& r2, uint32_t& r3) {
    asm volatile("ldmatrix.sync.aligned.m8n8.x4.shared.b16 {%0,%1,%2,%3}, [%4];"
        : "=r"(r0), "=r"(r1), "=r"(r2), "=r"(r3) : "r"(addr));
}
__device__ __forceinline__ void mma_bf16(float* c, const uint32_t* a, const uint32_t* b) {
    asm volatile("mma.sync.aligned.m16n8k16.row.col.f32.bf16.bf16.f32 "
        "{%0,%1,%2,%3}, {%4,%5,%6,%7}, {%8,%9}, {%0,%1,%2,%3};"
        : "+f"(c[0]), "+f"(c[1]), "+f"(c[2]), "+f"(c[3])
        : "r"(a[0]), "r"(a[1]), "r"(a[2]), "r"(a[3]), "r"(b[0]), "r"(b[1]));
}
__device__ __forceinline__ uint32_t pack_bf16(float lo, float hi) {
    uint32_t pk;
    asm("cvt.rn.bf16x2.f32 %0, %1, %2;" : "=r"(pk) : "f"(hi), "f"(lo));
    return pk;
}

// ---------------- prep kernels ----------------------------------------------
__global__ void prep_g0(const float* __restrict__ Wh, const float* __restrict__ Win) {
    int i = blockIdx.x, d = threadIdx.x;
    float acc = 0.f;
    for (int j = 0; j < HID; j++) acc += Wh[i * HID + j] * Win[j * NDIM + d];
    g_G0[i * NDIM + d] = acc;
}
__global__ void prep_wt(const float* __restrict__ Wh) {
    int li = blockIdx.x >> 9, n = blockIdx.x & 511;
    const float* base = Wh + (size_t)(li + 1) * HID * HID;
    __nv_bfloat16* dst = g_WT[li] + (size_t)n * HID;
    for (int k = threadIdx.x; k < HID; k += 128)
        dst[k] = __float2bfloat16(base[(size_t)k * HID + n]);
}
__global__ void prep_g0t() {
    int d = blockIdx.x, h = threadIdx.x;
    g_G0T[d * HID + h] = __float2bfloat16(g_G0[h * NDIM + d]);
}

// ---------------- forward both branches + masks + JVP -----------------------
__global__ __launch_bounds__(512) void fwd_kernel(
    const float* __restrict__ x,
    const float* __restrict__ Win, const float* __restrict__ bin,
    const float* __restrict__ Wh,  const float* __restrict__ bh,
    const float* __restrict__ Wout, const float* __restrict__ bout,
    float* __restrict__ out)
{
    extern __shared__ float sm[];
    float* sxA = sm;
    float* sxZ = sxA + GB * NDIM;
    float* sxD = sxZ + GB * NDIM;
    float* shA = sxD + GB * NDIM;
    float* shB = shA + GB * HID;
    float* sv  = shB + GB * HID;

    int t  = threadIdx.x;
    int b0 = blockIdx.x * GB;

    for (int i = t; i < GB * 192; i += 512) {
        int g = i / 192, c = i % 192;
        float v = x[(b0 + g) * 192 + c];
        if (c < 64)       sxA[g * NDIM + c] = v;
        else if (c < 128) sxD[g * NDIM + (c - 64)] = v;
        else              sxZ[g * NDIM + (c - 128)] = v;
    }
    __syncthreads();

    {
        float aA[GB], aB[GB], aV[GB];
        float bi = bin[t];
#pragma unroll
        for (int g = 0; g < GB; g++) { aA[g] = bi; aB[g] = bi; aV[g] = 0.f; }
        for (int d = 0; d < NDIM; d++) {
            float w  = Win[t * NDIM + d];
            float g0 = g_G0[t * NDIM + d];
#pragma unroll
            for (int g = 0; g < GB; g++) {
                aA[g] += w  * sxA[g * NDIM + d];
                aB[g] += w  * sxZ[g * NDIM + d];
                aV[g] += g0 * sxD[g * NDIM + d];
            }
        }
#pragma unroll
        for (int g = 0; g < GB; g++) {
            shA[g * HID + t] = aA[g];
            shB[g * HID + t] = aB[g];
            sv [g * HID + t] = aV[g];
        }
    }
    __syncthreads();

#pragma unroll
    for (int l = 0; l < 3; l++) {
        const float* W = Wh + (size_t)l * HID * HID;
        const float4* Wr = (const float4*)(W + t * HID);
        float bias = bh[l * HID + t];

        float aA[GB], aB[GB], aV[GB];
#pragma unroll
        for (int g = 0; g < GB; g++) { aA[g] = bias; aB[g] = bias; aV[g] = 0.f; }
#pragma unroll 4
        for (int k4 = 0; k4 < HID / 4; k4++) {
            float4 w4 = Wr[k4];
            int k = k4 * 4;
#pragma unroll
            for (int q = 0; q < 4; q++) {
                float w = (&w4.x)[q];
#pragma unroll
                for (int g = 0; g < GB; g++) {
                    aA[g] += w * shA[g * HID + k + q];
                    aB[g] += w * shB[g * HID + k + q];
                    if (l > 0) aV[g] += w * sv[g * HID + k + q];
                }
            }
        }
        __syncthreads();
#pragma unroll
        for (int g = 0; g < GB; g++) {
            shA[g * HID + t] = fmaxf(aA[g], 0.f);
            shB[g * HID + t] = fmaxf(aB[g], 0.f);
            if (l > 0) sv[g * HID + t] = aV[g];
        }
        __syncthreads();

#pragma unroll
        for (int g = 0; g < GB; g++) { aA[g] = bias; aB[g] = bias; }
#pragma unroll 4
        for (int k4 = 0; k4 < HID / 4; k4++) {
            float4 w4 = Wr[k4];
            int k = k4 * 4;
#pragma unroll
            for (int q = 0; q < 4; q++) {
                float w = (&w4.x)[q];
#pragma unroll
                for (int g = 0; g < GB; g++) {
                    aA[g] += w * shA[g * HID + k + q];
                    aB[g] += w * shB[g * HID + k + q];
                }
            }
        }
#pragma unroll
        for (int g = 0; g < GB; g++) {
            float dA = aA[g] > 0.f ? 1.f : 0.f;
            float dB = aB[g] > 0.f ? 1.f : 0.f;
            sv[g * HID + t] *= dA;
            g_maskB[((size_t)l * BATCH + (b0 + g)) * HID + t] = dB;
        }
        __syncthreads();
    }

    {
        int n = t >> 3, s = t & 7;
        float aO[GB], aV[GB];
#pragma unroll
        for (int g = 0; g < GB; g++) { aO[g] = 0.f; aV[g] = 0.f; }
        for (int h = s * 64; h < s * 64 + 64; h++) {
            float w = Wout[n * HID + h];
#pragma unroll
            for (int g = 0; g < GB; g++) {
                aO[g] += w * shA[g * HID + h];
                aV[g] += w * sv [g * HID + h];
            }
        }
        float* red = shB;
#pragma unroll
        for (int g = 0; g < GB; g++) red[(g * 64 + n) * 8 + s] = aO[g];
        __syncthreads();
        if (s == 0) {
#pragma unroll
            for (int g = 0; g < GB; g++) {
                float sum = bout[n];
                for (int ss = 0; ss < 8; ss++) sum += red[(g * 64 + n) * 8 + ss];
                out[(size_t)(b0 + g) * 192 + n] = sum;
            }
        }
        __syncthreads();
#pragma unroll
        for (int g = 0; g < GB; g++) red[(g * 64 + n) * 8 + s] = aV[g];
        __syncthreads();
        if (s == 0) {
#pragma unroll
            for (int g = 0; g < GB; g++) {
                float sum = 0.f;
                for (int ss = 0; ss < 8; ss++) sum += red[(g * 64 + n) * 8 + ss];
                out[(size_t)(b0 + g) * 192 + 64 + n] = sum;
            }
        }
    }
}

// ---------------- z_kernel: HMMA Jacobian chain ------------------------------
// issue one B chunk: rows [ns*128, +128) x cols [kc*64, +64) of Bg[n][512]
__device__ __forceinline__ void issue_b128(const __nv_bfloat16* __restrict__ Bg,
                                           int ns, int kc, uint32_t sB, int t) {
#pragma unroll
    for (int i = 0; i < 4; i++) {
        int flat = t + 256 * i;
        int row = flat >> 3, seg = flat & 7;
        CP16(sB + row * B_STRIDE + seg * 16,
             (const char*)(Bg + (size_t)(ns * 128 + row) * HID + kc * 64 + seg * 8));
    }
    CP_COMMIT();
}

// one 128x512x512 GEMM: sA (bf16) @ Bg^T-layout, mask cols, result -> Ug, then Ug -> sA
__device__ void gemm512(const __nv_bfloat16* __restrict__ Bg,
                        const float* __restrict__ mb,      // masks: [item*512 + col]
                        __nv_bfloat16* __restrict__ Ug,
                        uint32_t smu, int t)
{
    const int w = t >> 5, l = t & 31;
    const int wm = w & 3, wn = w >> 2;
    const uint32_t sA = smu + ZP_A;
    const uint32_t aRowB = (wm * 32 + (l & 15)) * A_STRIDE + ((l >> 4) << 4); // +8 elems = 16B
    const uint32_t bRowB = ((l & 7) + ((l >> 4) << 3)) * B_STRIDE + (((l >> 3) & 1) << 4);

#pragma unroll 1
    for (int ns = 0; ns < 4; ns++) {
        float c[2][8][4];
#pragma unroll
        for (int mt = 0; mt < 2; mt++)
#pragma unroll
            for (int nt = 0; nt < 8; nt++)
#pragma unroll
                for (int q = 0; q < 4; q++) c[mt][nt][q] = 0.f;

        issue_b128(Bg, ns, 0, smu + ZP_B, t);
        issue_b128(Bg, ns, 1, smu + ZP_B + 18432, t);

#pragma unroll
        for (int kc = 0; kc < 8; kc++) {
            if (kc == 7) { CP_WAIT(0); } else { CP_WAIT(1); }
            __syncthreads();
            uint32_t sB = smu + ZP_B + (kc & 1) * 18432;
#pragma unroll
            for (int ks = 0; ks < 4; ks++) {
                uint32_t a[2][4];
#pragma unroll
                for (int mt = 0; mt < 2; mt++)
                    ldsm4(sA + aRowB + mt * 16 * A_STRIDE + (kc * 64 + ks * 16) * 2,
                          a[mt][0], a[mt][1], a[mt][2], a[mt][3]);
                uint32_t b[8][2];
#pragma unroll
                for (int p = 0; p < 4; p++) {
                    uint32_t addr = sB + (wn * 64 + p * 16) * B_STRIDE + bRowB + ks * 32;
                    uint32_t r0, r1, r2, r3;
                    ldsm4(addr, r0, r1, r2, r3);
                    b[2 * p][0] = r0; b[2 * p][1] = r1;
                    b[2 * p + 1][0] = r2; b[2 * p + 1][1] = r3;
                }
#pragma unroll
                for (int mt = 0; mt < 2; mt++)
#pragma unroll
                    for (int nt = 0; nt < 8; nt++)
                        mma_bf16(c[mt][nt], a[mt], b[nt]);
            }
            __syncthreads();
            if (kc + 2 < 8) issue_b128(Bg, ns, kc + 2, smu + ZP_B + (kc & 1) * 18432, t);
        }

        // masked bf16 write to Ug
#pragma unroll
        for (int mt = 0; mt < 2; mt++) {
            int r0 = wm * 32 + mt * 16 + (l >> 2);
            const float* mk = mb + ((wm * 32 + mt * 16) >> 6) * HID;
#pragma unroll
            for (int nt = 0; nt < 8; nt++) {
                int col = ns * 128 + wn * 64 + nt * 8 + (l & 3) * 2;
                float m0 = mk[col], m1 = mk[col + 1];
                *(uint32_t*)&Ug[(size_t)r0 * HID + col] =
                    pack_bf16(c[mt][nt][0] * m0, c[mt][nt][1] * m1);
                *(uint32_t*)&Ug[(size_t)(r0 + 8) * HID + col] =
                    pack_bf16(c[mt][nt][2] * m0, c[mt][nt][3] * m1);
            }
        }
    }
    __syncthreads();    // all Ug writes done (visible block-wide)

    // Ug -> sA (padded layout)
#pragma unroll
    for (int i = 0; i < 32; i++) {
        int flat = t + 256 * i;
        int row = flat >> 6, seg = flat & 63;
        CP16(sA + row * A_STRIDE + seg * 16, (const char*)(Ug + (size_t)row * HID + seg * 8));
    }
    CP_COMMIT();
    CP_WAIT(0);
    __syncthreads();
}

// final: J = sA(128x512) @ G0T^T -> 128x64, then row-norms -> out
__device__ void gemm_final(const __nv_bfloat16* __restrict__ Bg,
                           float* __restrict__ out, int b0, uint32_t smu, int t)
{
    const int w = t >> 5, l = t & 31;
    const uint32_t sA = smu + ZP_A;
    const uint32_t aRowB = (w * 16 + (l & 15)) * A_STRIDE + ((l >> 4) << 4);
    const uint32_t bRowB = ((l & 7) + ((l >> 4) << 3)) * B_STRIDE + (((l >> 3) & 1) << 4);

    float c[8][4];
#pragma unroll
    for (int nt = 0; nt < 8; nt++)
#pragma unroll
        for (int q = 0; q < 4; q++) c[nt][q] = 0.f;

    // issue chunk kc: 64 rows x 64 cols
    auto issue64 = [&](int kc, uint32_t sB) {
#pragma unroll
        for (int i = 0; i < 2; i++) {
            int flat = t + 256 * i;
            int row = flat >> 3, seg = flat & 7;
            CP16(sB + row * B_STRIDE + seg * 16,
                 (const char*)(Bg + (size_t)row * HID + kc * 64 + seg * 8));
        }
        CP_COMMIT();
    };

    issue64(0, smu + ZP_B);
    issue64(1, smu + ZP_B + 18432);

#pragma unroll
    for (int kc = 0; kc < 8; kc++) {
        if (kc == 7) { CP_WAIT(0); } else { CP_WAIT(1); }
        __syncthreads();
        uint32_t sB = smu + ZP_B + (kc & 1) * 18432;
#pragma unroll
        for (int ks = 0; ks < 4; ks++) {
            uint32_t a[4];
            ldsm4(sA + aRowB + (kc * 64 + ks * 16) * 2, a[0], a[1], a[2], a[3]);
            uint32_t b[8][2];
#pragma unroll
            for (int p = 0; p < 4; p++) {
                uint32_t addr = sB + (p * 16) * B_STRIDE + bRowB + ks * 32;
                uint32_t r0, r1, r2, r3;
                ldsm4(addr, r0, r1, r2, r3);
                b[2 * p][0] = r0; b[2 * p][1] = r1;
                b[2 * p + 1][0] = r2; b[2 * p + 1][1] = r3;
            }
#pragma unroll
            for (int nt = 0; nt < 8; nt++)
                mma_bf16(c[nt], a, b[nt]);
        }
        __syncthreads();
        if (kc + 2 < 8) issue64(kc + 2, smu + ZP_B + (kc & 1) * 18432);
    }

    float s0 = 0.f, s1 = 0.f;
#pragma unroll
    for (int nt = 0; nt < 8; nt++) {
        s0 += c[nt][0] * c[nt][0] + c[nt][1] * c[nt][1];
        s1 += c[nt][2] * c[nt][2] + c[nt][3] * c[nt][3];
    }
    s0 += __shfl_xor_sync(0xFFFFFFFF, s0, 1);
    s0 += __shfl_xor_sync(0xFFFFFFFF, s0, 2);
    s1 += __shfl_xor_sync(0xFFFFFFFF, s1, 1);
    s1 += __shfl_xor_sync(0xFFFFFFFF, s1, 2);
    if ((l & 3) == 0) {
        int r0 = w * 16 + (l >> 2);
        out[(size_t)(b0 + (r0 >> 6)) * 192 + 128 + (r0 & 63)] = sqrtf(s0);
        int r1 = r0 + 8;
        out[(size_t)(b0 + (r1 >> 6)) * 192 + 128 + (r1 & 63)] = sqrtf(s1);
    }
}

__global__ __launch_bounds__(256) void z_kernel(const float* __restrict__ Wout,
                                                float* __restrict__ out)
{
    extern __shared__ char smc[];
    uint32_t smu = smem_u32(smc);
    int t = threadIdx.x;
    int b0 = blockIdx.x * 2;

    float* msk = (float*)(smc + ZP_MSK);   // [(layer*2+item)*512 + h]
    for (int i = t; i < 6 * HID; i += 256) {
        int layer = i >> 10, r = i & 1023, item = r >> 9, h = r & 511;
        msk[i] = g_maskB[((size_t)layer * BATCH + b0 + item) * HID + h];
    }
    __syncthreads();

    // U1 = Wout ∘ delta3 -> sA (padded row-major bf16)
    char* sAc = smc + ZP_A;
    for (int i = t; i < 128 * 256; i += 256) {
        int m = i >> 8, p = i & 255;
        int h = p * 2;
        int item = m >> 6, n = m & 63;
        const float* d3 = msk + (4 + item) * HID;
        *(uint32_t*)(sAc + m * A_STRIDE + h * 2) =
            pack_bf16(Wout[n * HID + h] * d3[h], Wout[n * HID + h + 1] * d3[h + 1]);
    }

    __nv_bfloat16* Ug = g_U + (size_t)blockIdx.x * 128 * HID;
    gemm512(g_WT[1], msk + 2 * HID, Ug, smu, t);   // U2 = (U1 @ Wh2) ∘ d2
    gemm512(g_WT[0], msk,           Ug, smu, t);   // U3 = (U2 @ Wh1) ∘ d1
    gemm_final(g_G0T, out, b0, smu, t);            // J = U3 @ G0^T, norms
}

// ---------------- launch ----------------------------------------------------
extern "C" void kernel_launch(void* const* d_in, const int* in_sizes, int n_in,
                              void* d_out, int out_size)
{
    const float* x    = (const float*)d_in[0];
    const float* Win  = (const float*)d_in[1];
    const float* bin  = (const float*)d_in[2];
    const float* Wh   = (const float*)d_in[3];
    const float* bh   = (const float*)d_in[4];
    const float* Wout = (const float*)d_in[5];
    const float* bout = (const float*)d_in[6];
    float* out = (float*)d_out;

    int B = in_sizes[0] / 192;   // 4096

    const int fwd_smem = (GB * (3 * NDIM + 3 * HID)) * sizeof(float);
    cudaFuncSetAttribute(fwd_kernel, cudaFuncAttributeMaxDynamicSharedMemorySize, fwd_smem);
    cudaFuncSetAttribute(z_kernel,   cudaFuncAttributeMaxDynamicSharedMemorySize, Z_SMEM);

    prep_g0<<<HID, NDIM>>>(Wh, Win);
    prep_wt<<<1024, 128>>>(Wh);
    prep_g0t<<<NDIM, HID>>>();
    fwd_kernel<<<B / GB, 512, fwd_smem>>>(x, Win, bin, Wh, bh, Wout, bout, out);
    z_kernel<<<B / 2, 256, Z_SMEM>>>(Wout, out);
}

// round 4
// speedup vs baseline: 3.8771x; 1.0038x over previous
#include <cuda_runtime.h>
#include <cuda_bf16.h>
#include <math.h>
#include <stdint.h>

#define BATCH 4096
#define NDIM  64
#define HID   512
#define GB    8

// ---------------- device globals (static: allocation APIs are banned) -------
__device__ float g_G0[HID * NDIM];                          // G0 = Wh0 @ Win (fp32)
__device__ float g_maskB[3 * BATCH * HID];                  // zero-branch masks
__device__ __align__(16) __nv_bfloat16 g_WT[2][HID * HID];  // Wh1^T, Wh2^T  [n][k]
__device__ __align__(16) __nv_bfloat16 g_G0T[NDIM * HID];   // G0^T [d][h]
__device__ __align__(16) __nv_bfloat16 g_U[(size_t)(BATCH / 2) * 128 * HID]; // U staging

// ---------------- SMEM map for z_kernel (bytes) -----------------------------
#define ZP_MSK   0                       // 6*512 fp32 = 12288
#define ZP_A     12288                   // 128 rows * 520 bf16 = 133120
#define ZP_B     145408                  // 2 * (128 * 144B) = 36864
#define Z_SMEM   182272
#define A_STRIDE 1040                    // bytes per A row (520 bf16)
#define B_STRIDE 144                     // bytes per B row (72 bf16)

// ---------------- asm helpers ------------------------------------------------
__device__ __forceinline__ uint32_t smem_u32(const void* p) {
    uint32_t a;
    asm("{ .reg .u64 t; cvta.to.shared.u64 t, %1; cvt.u32.u64 %0, t; }" : "=r"(a) : "l"(p));
    return a;
}
#define CP16(dst, src)  asm volatile("cp.async.cg.shared.global [%0], [%1], 16;" :: "r"(dst), "l"(src))
#define CP_COMMIT()     asm volatile("cp.async.commit_group;" ::: "memory")
#define CP_WAIT(n)      asm volatile("cp.async.wait_group %0;" :: "n"(n) : "memory")

__device__ __forceinline__ void ldsm4(uint32_t addr, uint32_t& r0, uint32_t& r1,
                                      uint32_t& r2, uint32_t& r3) {
    asm volatile("ldmatrix.sync.aligned.m8n8.x4.shared.b16 {%0,%1,%2,%3}, [%4];"
        : "=r"(r0), "=r"(r1), "=r"(r2), "=r"(r3) : "r"(addr));
}
__device__ __forceinline__ void mma_bf16(float* c, const uint32_t* a, const uint32_t* b) {
    asm volatile("mma.sync.aligned.m16n8k16.row.col.f32.bf16.bf16.f32 "
        "{%0,%1,%2,%3}, {%4,%5,%6,%7}, {%8,%9}, {%0,%1,%2,%3};"
        : "+f"(c[0]), "+f"(c[1]), "+f"(c[2]), "+f"(c[3])
        : "r"(a[0]), "r"(a[1]), "r"(a[2]), "r"(a[3]), "r"(b[0]), "r"(b[1]));
}
__device__ __forceinline__ uint32_t pack_bf16(float lo, float hi) {
    uint32_t pk;
    asm("cvt.rn.bf16x2.f32 %0, %1, %2;" : "=r"(pk) : "f"(hi), "f"(lo));
    return pk;
}

// ---------------- prep kernels ----------------------------------------------
__global__ void prep_g0(const float* __restrict__ Wh, const float* __restrict__ Win) {
    int i = blockIdx.x, d = threadIdx.x;
    float acc = 0.f;
    for (int j = 0; j < HID; j++) acc += Wh[i * HID + j] * Win[j * NDIM + d];
    g_G0[i * NDIM + d] = acc;
}
__global__ void prep_wt(const float* __restrict__ Wh) {
    int li = blockIdx.x >> 9, n = blockIdx.x & 511;
    const float* base = Wh + (size_t)(li + 1) * HID * HID;
    __nv_bfloat16* dst = g_WT[li] + (size_t)n * HID;
    for (int k = threadIdx.x; k < HID; k += 128)
        dst[k] = __float2bfloat16(base[(size_t)k * HID + n]);
}
__global__ void prep_g0t() {
    int d = blockIdx.x, h = threadIdx.x;
    g_G0T[d * HID + h] = __float2bfloat16(g_G0[h * NDIM + d]);
}

// ---------------- forward both branches + masks + JVP -----------------------
__global__ __launch_bounds__(512) void fwd_kernel(
    const float* __restrict__ x,
    const float* __restrict__ Win, const float* __restrict__ bin,
    const float* __restrict__ Wh,  const float* __restrict__ bh,
    const float* __restrict__ Wout, const float* __restrict__ bout,
    float* __restrict__ out)
{
    extern __shared__ float sm[];
    float* sxA = sm;
    float* sxZ = sxA + GB * NDIM;
    float* sxD = sxZ + GB * NDIM;
    float* shA = sxD + GB * NDIM;
    float* shB = shA + GB * HID;
    float* sv  = shB + GB * HID;

    int t  = threadIdx.x;
    int b0 = blockIdx.x * GB;

    for (int i = t; i < GB * 192; i += 512) {
        int g = i / 192, c = i % 192;
        float v = x[(b0 + g) * 192 + c];
        if (c < 64)       sxA[g * NDIM + c] = v;
        else if (c < 128) sxD[g * NDIM + (c - 64)] = v;
        else              sxZ[g * NDIM + (c - 128)] = v;
    }
    __syncthreads();

    {
        float aA[GB], aB[GB], aV[GB];
        float bi = bin[t];
#pragma unroll
        for (int g = 0; g < GB; g++) { aA[g] = bi; aB[g] = bi; aV[g] = 0.f; }
        for (int d = 0; d < NDIM; d++) {
            float w  = Win[t * NDIM + d];
            float g0 = g_G0[t * NDIM + d];
#pragma unroll
            for (int g = 0; g < GB; g++) {
                aA[g] += w  * sxA[g * NDIM + d];
                aB[g] += w  * sxZ[g * NDIM + d];
                aV[g] += g0 * sxD[g * NDIM + d];
            }
        }
#pragma unroll
        for (int g = 0; g < GB; g++) {
            shA[g * HID + t] = aA[g];
            shB[g * HID + t] = aB[g];
            sv [g * HID + t] = aV[g];
        }
    }
    __syncthreads();

#pragma unroll
    for (int l = 0; l < 3; l++) {
        const float* W = Wh + (size_t)l * HID * HID;
        const float4* Wr = (const float4*)(W + t * HID);
        float bias = bh[l * HID + t];

        float aA[GB], aB[GB], aV[GB];
#pragma unroll
        for (int g = 0; g < GB; g++) { aA[g] = bias; aB[g] = bias; aV[g] = 0.f; }
#pragma unroll 4
        for (int k4 = 0; k4 < HID / 4; k4++) {
            float4 w4 = Wr[k4];
            int k = k4 * 4;
#pragma unroll
            for (int q = 0; q < 4; q++) {
                float w = (&w4.x)[q];
#pragma unroll
                for (int g = 0; g < GB; g++) {
                    aA[g] += w * shA[g * HID + k + q];
                    aB[g] += w * shB[g * HID + k + q];
                    if (l > 0) aV[g] += w * sv[g * HID + k + q];
                }
            }
        }
        __syncthreads();
#pragma unroll
        for (int g = 0; g < GB; g++) {
            shA[g * HID + t] = fmaxf(aA[g], 0.f);
            shB[g * HID + t] = fmaxf(aB[g], 0.f);
            if (l > 0) sv[g * HID + t] = aV[g];
        }
        __syncthreads();

#pragma unroll
        for (int g = 0; g < GB; g++) { aA[g] = bias; aB[g] = bias; }
#pragma unroll 4
        for (int k4 = 0; k4 < HID / 4; k4++) {
            float4 w4 = Wr[k4];
            int k = k4 * 4;
#pragma unroll
            for (int q = 0; q < 4; q++) {
                float w = (&w4.x)[q];
#pragma unroll
                for (int g = 0; g < GB; g++) {
                    aA[g] += w * shA[g * HID + k + q];
                    aB[g] += w * shB[g * HID + k + q];
                }
            }
        }
#pragma unroll
        for (int g = 0; g < GB; g++) {
            float dA = aA[g] > 0.f ? 1.f : 0.f;
            float dB = aB[g] > 0.f ? 1.f : 0.f;
            sv[g * HID + t] *= dA;
            g_maskB[((size_t)l * BATCH + (b0 + g)) * HID + t] = dB;
        }
        __syncthreads();
    }

    {
        int n = t >> 3, s = t & 7;
        float aO[GB], aV[GB];
#pragma unroll
        for (int g = 0; g < GB; g++) { aO[g] = 0.f; aV[g] = 0.f; }
        for (int h = s * 64; h < s * 64 + 64; h++) {
            float w = Wout[n * HID + h];
#pragma unroll
            for (int g = 0; g < GB; g++) {
                aO[g] += w * shA[g * HID + h];
                aV[g] += w * sv [g * HID + h];
            }
        }
        float* red = shB;
#pragma unroll
        for (int g = 0; g < GB; g++) red[(g * 64 + n) * 8 + s] = aO[g];
        __syncthreads();
        if (s == 0) {
#pragma unroll
            for (int g = 0; g < GB; g++) {
                float sum = bout[n];
                for (int ss = 0; ss < 8; ss++) sum += red[(g * 64 + n) * 8 + ss];
                out[(size_t)(b0 + g) * 192 + n] = sum;
            }
        }
        __syncthreads();
#pragma unroll
        for (int g = 0; g < GB; g++) red[(g * 64 + n) * 8 + s] = aV[g];
        __syncthreads();
        if (s == 0) {
#pragma unroll
            for (int g = 0; g < GB; g++) {
                float sum = 0.f;
                for (int ss = 0; ss < 8; ss++) sum += red[(g * 64 + n) * 8 + ss];
                out[(size_t)(b0 + g) * 192 + 64 + n] = sum;
            }
        }
    }
}

// ---------------- z_kernel: HMMA Jacobian chain ------------------------------
// issue one B chunk: rows [ns*128, +128) x cols [kc*64, +64) of Bg[n][512]
__device__ __forceinline__ void issue_b128(const __nv_bfloat16* __restrict__ Bg,
                                           int ns, int kc, uint32_t sB, int t) {
#pragma unroll
    for (int i = 0; i < 4; i++) {
        int flat = t + 256 * i;
        int row = flat >> 3, seg = flat & 7;
        CP16(sB + row * B_STRIDE + seg * 16,
             (const char*)(Bg + (size_t)(ns * 128 + row) * HID + kc * 64 + seg * 8));
    }
    CP_COMMIT();
}

// one 128x512x512 GEMM: sA (bf16) @ Bg^T-layout, mask cols, result -> Ug, then Ug -> sA
__device__ void gemm512(const __nv_bfloat16* __restrict__ Bg,
                        const float* __restrict__ mb,      // masks: [item*512 + col]
                        __nv_bfloat16* __restrict__ Ug,
                        uint32_t smu, int t)
{
    const int w = t >> 5, l = t & 31;
    const int wm = w & 3, wn = w >> 2;
    const uint32_t sA = smu + ZP_A;
    const uint32_t aRowB = (wm * 32 + (l & 15)) * A_STRIDE + ((l >> 4) << 4); // +8 elems = 16B
    const uint32_t bRowB = ((l & 7) + ((l >> 4) << 3)) * B_STRIDE + (((l >> 3) & 1) << 4);

#pragma unroll 1
    for (int ns = 0; ns < 4; ns++) {
        float c[2][8][4];
#pragma unroll
        for (int mt = 0; mt < 2; mt++)
#pragma unroll
            for (int nt = 0; nt < 8; nt++)
#pragma unroll
                for (int q = 0; q < 4; q++) c[mt][nt][q] = 0.f;

        issue_b128(Bg, ns, 0, smu + ZP_B, t);
        issue_b128(Bg, ns, 1, smu + ZP_B + 18432, t);

#pragma unroll
        for (int kc = 0; kc < 8; kc++) {
            if (kc == 7) { CP_WAIT(0); } else { CP_WAIT(1); }
            __syncthreads();
            uint32_t sB = smu + ZP_B + (kc & 1) * 18432;
#pragma unroll
            for (int ks = 0; ks < 4; ks++) {
                uint32_t a[2][4];
#pragma unroll
                for (int mt = 0; mt < 2; mt++)
                    ldsm4(sA + aRowB + mt * 16 * A_STRIDE + (kc * 64 + ks * 16) * 2,
                          a[mt][0], a[mt][1], a[mt][2], a[mt][3]);
                uint32_t b[8][2];
#pragma unroll
                for (int p = 0; p < 4; p++) {
                    uint32_t addr = sB + (wn * 64 + p * 16) * B_STRIDE + bRowB + ks * 32;
                    uint32_t r0, r1, r2, r3;
                    ldsm4(addr, r0, r1, r2, r3);
                    b[2 * p][0] = r0; b[2 * p][1] = r1;
                    b[2 * p + 1][0] = r2; b[2 * p + 1][1] = r3;
                }
#pragma unroll
                for (int mt = 0; mt < 2; mt++)
#pragma unroll
                    for (int nt = 0; nt < 8; nt++)
                        mma_bf16(c[mt][nt], a[mt], b[nt]);
            }
            __syncthreads();
            if (kc + 2 < 8) issue_b128(Bg, ns, kc + 2, smu + ZP_B + (kc & 1) * 18432, t);
        }

        // masked bf16 write to Ug
#pragma unroll
        for (int mt = 0; mt < 2; mt++) {
            int r0 = wm * 32 + mt * 16 + (l >> 2);
            const float* mk = mb + ((wm * 32 + mt * 16) >> 6) * HID;
#pragma unroll
            for (int nt = 0; nt < 8; nt++) {
                int col = ns * 128 + wn * 64 + nt * 8 + (l & 3) * 2;
                float m0 = mk[col], m1 = mk[col + 1];
                *(uint32_t*)&Ug[(size_t)r0 * HID + col] =
                    pack_bf16(c[mt][nt][0] * m0, c[mt][nt][1] * m1);
                *(uint32_t*)&Ug[(size_t)(r0 + 8) * HID + col] =
                    pack_bf16(c[mt][nt][2] * m0, c[mt][nt][3] * m1);
            }
        }
    }
    __syncthreads();    // all Ug writes done (visible block-wide)

    // Ug -> sA (padded layout)
#pragma unroll
    for (int i = 0; i < 32; i++) {
        int flat = t + 256 * i;
        int row = flat >> 6, seg = flat & 63;
        CP16(sA + row * A_STRIDE + seg * 16, (const char*)(Ug + (size_t)row * HID + seg * 8));
    }
    CP_COMMIT();
    CP_WAIT(0);
    __syncthreads();
}

// final: J = sA(128x512) @ G0T^T -> 128x64, then row-norms -> out
__device__ void gemm_final(const __nv_bfloat16* __restrict__ Bg,
                           float* __restrict__ out, int b0, uint32_t smu, int t)
{
    const int w = t >> 5, l = t & 31;
    const uint32_t sA = smu + ZP_A;
    const uint32_t aRowB = (w * 16 + (l & 15)) * A_STRIDE + ((l >> 4) << 4);
    const uint32_t bRowB = ((l & 7) + ((l >> 4) << 3)) * B_STRIDE + (((l >> 3) & 1) << 4);

    float c[8][4];
#pragma unroll
    for (int nt = 0; nt < 8; nt++)
#pragma unroll
        for (int q = 0; q < 4; q++) c[nt][q] = 0.f;

    // issue chunk kc: 64 rows x 64 cols
    auto issue64 = [&](int kc, uint32_t sB) {
#pragma unroll
        for (int i = 0; i < 2; i++) {
            int flat = t + 256 * i;
            int row = flat >> 3, seg = flat & 7;
            CP16(sB + row * B_STRIDE + seg * 16,
                 (const char*)(Bg + (size_t)row * HID + kc * 64 + seg * 8));
        }
        CP_COMMIT();
    };

    issue64(0, smu + ZP_B);
    issue64(1, smu + ZP_B + 18432);

#pragma unroll
    for (int kc = 0; kc < 8; kc++) {
        if (kc == 7) { CP_WAIT(0); } else { CP_WAIT(1); }
        __syncthreads();
        uint32_t sB = smu + ZP_B + (kc & 1) * 18432;
#pragma unroll
        for (int ks = 0; ks < 4; ks++) {
            uint32_t a[4];
            ldsm4(sA + aRowB + (kc * 64 + ks * 16) * 2, a[0], a[1], a[2], a[3]);
            uint32_t b[8][2];
#pragma unroll
            for (int p = 0; p < 4; p++) {
                uint32_t addr = sB + (p * 16) * B_STRIDE + bRowB + ks * 32;
                uint32_t r0, r1, r2, r3;
                ldsm4(addr, r0, r1, r2, r3);
                b[2 * p][0] = r0; b[2 * p][1] = r1;
                b[2 * p + 1][0] = r2; b[2 * p + 1][1] = r3;
            }
#pragma unroll
            for (int nt = 0; nt < 8; nt++)
                mma_bf16(c[nt], a, b[nt]);
        }
        __syncthreads();
        if (kc + 2 < 8) issue64(kc + 2, smu + ZP_B + (kc & 1) * 18432);
    }

    float s0 = 0.f, s1 = 0.f;
#pragma unroll
    for (int nt = 0; nt < 8; nt++) {
        s0 += c[nt][0] * c[nt][0] + c[nt][1] * c[nt][1];
        s1 += c[nt][2] * c[nt][2] + c[nt][3] * c[nt][3];
    }
    s0 += __shfl_xor_sync(0xFFFFFFFF, s0, 1);
    s0 += __shfl_xor_sync(0xFFFFFFFF, s0, 2);
    s1 += __shfl_xor_sync(0xFFFFFFFF, s1, 1);
    s1 += __shfl_xor_sync(0xFFFFFFFF, s1, 2);
    if ((l & 3) == 0) {
        int r0 = w * 16 + (l >> 2);
        out[(size_t)(b0 + (r0 >> 6)) * 192 + 128 + (r0 & 63)] = sqrtf(s0);
        int r1 = r0 + 8;
        out[(size_t)(b0 + (r1 >> 6)) * 192 + 128 + (r1 & 63)] = sqrtf(s1);
    }
}

__global__ __launch_bounds__(256) void z_kernel(const float* __restrict__ Wout,
                                                float* __restrict__ out)
{
    extern __shared__ char smc[];
    uint32_t smu = smem_u32(smc);
    int t = threadIdx.x;
    int b0 = blockIdx.x * 2;

    float* msk = (float*)(smc + ZP_MSK);   // [(layer*2+item)*512 + h]
    for (int i = t; i < 6 * HID; i += 256) {
        int layer = i >> 10, r = i & 1023, item = r >> 9, h = r & 511;
        msk[i] = g_maskB[((size_t)layer * BATCH + b0 + item) * HID + h];
    }
    __syncthreads();

    // U1 = Wout ∘ delta3 -> sA (padded row-major bf16)
    char* sAc = smc + ZP_A;
    for (int i = t; i < 128 * 256; i += 256) {
        int m = i >> 8, p = i & 255;
        int h = p * 2;
        int item = m >> 6, n = m & 63;
        const float* d3 = msk + (4 + item) * HID;
        *(uint32_t*)(sAc + m * A_STRIDE + h * 2) =
            pack_bf16(Wout[n * HID + h] * d3[h], Wout[n * HID + h + 1] * d3[h + 1]);
    }

    __nv_bfloat16* Ug = g_U + (size_t)blockIdx.x * 128 * HID;
    gemm512(g_WT[1], msk + 2 * HID, Ug, smu, t);   // U2 = (U1 @ Wh2) ∘ d2
    gemm512(g_WT[0], msk,           Ug, smu, t);   // U3 = (U2 @ Wh1) ∘ d1
    gemm_final(g_G0T, out, b0, smu, t);            // J = U3 @ G0^T, norms
}

// ---------------- launch ----------------------------------------------------
extern "C" void kernel_launch(void* const* d_in, const int* in_sizes, int n_in,
                              void* d_out, int out_size)
{
    const float* x    = (const float*)d_in[0];
    const float* Win  = (const float*)d_in[1];
    const float* bin  = (const float*)d_in[2];
    const float* Wh   = (const float*)d_in[3];
    const float* bh   = (const float*)d_in[4];
    const float* Wout = (const float*)d_in[5];
    const float* bout = (const float*)d_in[6];
    float* out = (float*)d_out;

    int B = in_sizes[0] / 192;   // 4096

    const int fwd_smem = (GB * (3 * NDIM + 3 * HID)) * sizeof(float);
    cudaFuncSetAttribute(fwd_kernel, cudaFuncAttributeMaxDynamicSharedMemorySize, fwd_smem);
    cudaFuncSetAttribute(z_kernel,   cudaFuncAttributeMaxDynamicSharedMemorySize, Z_SMEM);

    prep_g0<<<HID, NDIM>>>(Wh, Win);
    prep_wt<<<1024, 128>>>(Wh);
    prep_g0t<<<NDIM, HID>>>();
    fwd_kernel<<<B / GB, 512, fwd_smem>>>(x, Win, bin, Wh, bh, Wout, bout, out);
    z_kernel<<<B / 2, 256, Z_SMEM>>>(Wout, out);
}

// round 9
// speedup vs baseline: 3.9399x; 1.0162x over previous
#include <cuda_runtime.h>
#include <cuda_bf16.h>
#include <math.h>
#include <stdint.h>

#define BATCH 4096
#define NDIM  64
#define HID   512
#define GB    8

// ---------------- device globals (static: allocation APIs are banned) -------
__device__ float g_G0[HID * NDIM];                          // G0 = Wh0 @ Win (fp32)
__device__ float g_maskB[3 * BATCH * HID];                  // zero-branch masks
__device__ __align__(16) __nv_bfloat16 g_WT[2][HID * HID];  // Wh1^T, Wh2^T  [n][k]
__device__ __align__(16) __nv_bfloat16 g_G0T[NDIM * HID];   // G0^T [d][h]
__device__ __align__(16) __nv_bfloat16 g_U[(size_t)(BATCH / 2) * 128 * HID]; // U staging

// ---------------- SMEM map for z_kernel (bytes) -----------------------------
#define ZP_MSK   0                       // 6*512 fp32 = 12288
#define ZP_A     12288                   // 128 rows * 520 bf16 = 133120
#define ZP_B     145408                  // 2 * (128 * 144B) = 36864
#define Z_SMEM   182272
#define A_STRIDE 1040                    // bytes per A row (520 bf16)
#define B_STRIDE 144                     // bytes per B row (72 bf16)

// ---------------- asm helpers ------------------------------------------------
__device__ __forceinline__ uint32_t smem_u32(const void* p) {
    uint32_t a;
    asm("{ .reg .u64 t; cvta.to.shared.u64 t, %1; cvt.u32.u64 %0, t; }" : "=r"(a) : "l"(p));
    return a;
}
#define CP16(dst, src)  asm volatile("cp.async.cg.shared.global [%0], [%1], 16;" :: "r"(dst), "l"(src))
#define CP_COMMIT()     asm volatile("cp.async.commit_group;" ::: "memory")
#define CP_WAIT(n)      asm volatile("cp.async.wait_group %0;" :: "n"(n) : "memory")

__device__ __forceinline__ void ldsm4(uint32_t addr, uint32_t& r0, uint32_t& r1,
                                      uint32_t& r2, uint32_t& r3) {
    asm volatile("ldmatrix.sync.aligned.m8n8.x4.shared.b16 {%0,%1,%2,%3}, [%4];"
        : "=r"(r0), "=r"(r1), "=r"(r2), "=r"(r3) : "r"(addr));
}
__device__ __forceinline__ void mma_bf16(float* c, const uint32_t* a, const uint32_t* b) {
    asm volatile("mma.sync.aligned.m16n8k16.row.col.f32.bf16.bf16.f32 "
        "{%0,%1,%2,%3}, {%4,%5,%6,%7}, {%8,%9}, {%0,%1,%2,%3};"
        : "+f"(c[0]), "+f"(c[1]), "+f"(c[2]), "+f"(c[3])
        : "r"(a[0]), "r"(a[1]), "r"(a[2]), "r"(a[3]), "r"(b[0]), "r"(b[1]));
}
__device__ __forceinline__ uint32_t pack_bf16(float lo, float hi) {
    uint32_t pk;
    asm("cvt.rn.bf16x2.f32 %0, %1, %2;" : "=r"(pk) : "f"(hi), "f"(lo));
    return pk;
}

// ---------------- prep kernels ----------------------------------------------
__global__ void prep_g0(const float* __restrict__ Wh, const float* __restrict__ Win) {
    int i = blockIdx.x, d = threadIdx.x;
    float acc = 0.f;
    for (int j = 0; j < HID; j++) acc += Wh[i * HID + j] * Win[j * NDIM + d];
    g_G0[i * NDIM + d] = acc;
}
__global__ void prep_wt(const float* __restrict__ Wh) {
    int li = blockIdx.x >> 9, n = blockIdx.x & 511;
    const float* base = Wh + (size_t)(li + 1) * HID * HID;
    __nv_bfloat16* dst = g_WT[li] + (size_t)n * HID;
    for (int k = threadIdx.x; k < HID; k += 128)
        dst[k] = __float2bfloat16(base[(size_t)k * HID + n]);
}
__global__ void prep_g0t() {
    int d = blockIdx.x, h = threadIdx.x;
    g_G0T[d * HID + h] = __float2bfloat16(g_G0[h * NDIM + d]);
}

// ---------------- forward: fp32 scalar, [h][g] SMEM layout -------------------
// Same math and summation order as the proven R1/R3 kernel; activations are
// stored transposed so the 8 batch values per k are one LDS.128 broadcast pair.
union F8 { float4 v[2]; float f[GB]; };

__global__ __launch_bounds__(512) void fwd_kernel(
    const float* __restrict__ x,
    const float* __restrict__ Win, const float* __restrict__ bin,
    const float* __restrict__ Wh,  const float* __restrict__ bh,
    const float* __restrict__ Wout, const float* __restrict__ bout,
    float* __restrict__ out)
{
    extern __shared__ float sm[];
    float* sxA = sm;                    // [64][8]
    float* sxZ = sxA + NDIM * GB;       // [64][8]
    float* sxD = sxZ + NDIM * GB;       // [64][8]
    float* shA = sxD + NDIM * GB;       // [512][8]
    float* shB = shA + HID * GB;        // [512][8]
    float* sv  = shB + HID * GB;        // [512][8]

    int t  = threadIdx.x;
    int b0 = blockIdx.x * GB;

    for (int i = t; i < GB * 192; i += 512) {
        int g = i / 192, c = i % 192;
        float v = x[(b0 + g) * 192 + c];
        if (c < 64)       sxA[c * GB + g] = v;
        else if (c < 128) sxD[(c - 64) * GB + g] = v;
        else              sxZ[(c - 128) * GB + g] = v;
    }
    __syncthreads();

    // h0 (no relu) both branches + v0 = G0 @ xtdot
    {
        float aA[GB], aB[GB], aV[GB];
        float bi = bin[t];
#pragma unroll
        for (int g = 0; g < GB; g++) { aA[g] = bi; aB[g] = bi; aV[g] = 0.f; }
        for (int d = 0; d < NDIM; d++) {
            float w  = Win[t * NDIM + d];
            float g0 = g_G0[t * NDIM + d];
            F8 xa, xz, xd;
            xa.v[0] = *(const float4*)&sxA[d * GB]; xa.v[1] = *(const float4*)&sxA[d * GB + 4];
            xz.v[0] = *(const float4*)&sxZ[d * GB]; xz.v[1] = *(const float4*)&sxZ[d * GB + 4];
            xd.v[0] = *(const float4*)&sxD[d * GB]; xd.v[1] = *(const float4*)&sxD[d * GB + 4];
#pragma unroll
            for (int g = 0; g < GB; g++) {
                aA[g] += w  * xa.f[g];
                aB[g] += w  * xz.f[g];
                aV[g] += g0 * xd.f[g];
            }
        }
#pragma unroll
        for (int g = 0; g < GB; g++) {
            shA[t * GB + g] = aA[g];
            shB[t * GB + g] = aB[g];
            sv [t * GB + g] = aV[g];
        }
    }
    __syncthreads();

#pragma unroll 1
    for (int l = 0; l < 3; l++) {
        const float* W = Wh + (size_t)l * HID * HID;
        const float4* Wr = (const float4*)(W + t * HID);
        float bias = bh[l * HID + t];

        // ---- pass 1: h_{l+1} = relu(W h_l + b); v = W v (layers 1,2) ----
        float aA[GB], aB[GB], aV[GB];
#pragma unroll
        for (int g = 0; g < GB; g++) { aA[g] = bias; aB[g] = bias; aV[g] = 0.f; }
#pragma unroll 4
        for (int k4 = 0; k4 < HID / 4; k4++) {
            float4 w4 = Wr[k4];
#pragma unroll
            for (int q = 0; q < 4; q++) {
                float w = (&w4.x)[q];
                int k = k4 * 4 + q;
                F8 ha, hb, vv;
                ha.v[0] = *(const float4*)&shA[k * GB]; ha.v[1] = *(const float4*)&shA[k * GB + 4];
                hb.v[0] = *(const float4*)&shB[k * GB]; hb.v[1] = *(const float4*)&shB[k * GB + 4];
                if (l > 0) {
                    vv.v[0] = *(const float4*)&sv[k * GB]; vv.v[1] = *(const float4*)&sv[k * GB + 4];
                }
#pragma unroll
                for (int g = 0; g < GB; g++) {
                    aA[g] += w * ha.f[g];
                    aB[g] += w * hb.f[g];
                    if (l > 0) aV[g] += w * vv.f[g];
                }
            }
        }
        __syncthreads();   // all reads done before overwriting
#pragma unroll
        for (int g = 0; g < GB; g++) {
            shA[t * GB + g] = fmaxf(aA[g], 0.f);
            shB[t * GB + g] = fmaxf(aB[g], 0.f);
            if (l > 0) sv[t * GB + g] = aV[g];
        }
        __syncthreads();

        // ---- pass 2: delta^{(l)} = (W h_{l+1} + b > 0)  (bug-faithful mask)
#pragma unroll
        for (int g = 0; g < GB; g++) { aA[g] = bias; aB[g] = bias; }
#pragma unroll 4
        for (int k4 = 0; k4 < HID / 4; k4++) {
            float4 w4 = Wr[k4];
#pragma unroll
            for (int q = 0; q < 4; q++) {
                float w = (&w4.x)[q];
                int k = k4 * 4 + q;
                F8 ha, hb;
                ha.v[0] = *(const float4*)&shA[k * GB]; ha.v[1] = *(const float4*)&shA[k * GB + 4];
                hb.v[0] = *(const float4*)&shB[k * GB]; hb.v[1] = *(const float4*)&shB[k * GB + 4];
#pragma unroll
                for (int g = 0; g < GB; g++) {
                    aA[g] += w * ha.f[g];
                    aB[g] += w * hb.f[g];
                }
            }
        }
#pragma unroll
        for (int g = 0; g < GB; g++) {
            float dA = aA[g] > 0.f ? 1.f : 0.f;
            float dB = aB[g] > 0.f ? 1.f : 0.f;
            sv[t * GB + g] *= dA;
            g_maskB[((size_t)l * BATCH + (b0 + g)) * HID + t] = dB;
        }
        __syncthreads();
    }

    // ---- final: h_out = Wout h3 + bout ; h_dot = Wout v -------------------
    {
        int n = t >> 3, s = t & 7;   // 64 n-groups x 8 slices of K
        float aO[GB], aV[GB];
#pragma unroll
        for (int g = 0; g < GB; g++) { aO[g] = 0.f; aV[g] = 0.f; }
        for (int h = s * 64; h < s * 64 + 64; h++) {
            float w = Wout[n * HID + h];
            F8 ha, vv;
            ha.v[0] = *(const float4*)&shA[h * GB]; ha.v[1] = *(const float4*)&shA[h * GB + 4];
            vv.v[0] = *(const float4*)&sv [h * GB]; vv.v[1] = *(const float4*)&sv [h * GB + 4];
#pragma unroll
            for (int g = 0; g < GB; g++) {
                aO[g] += w * ha.f[g];
                aV[g] += w * vv.f[g];
            }
        }
        float* red = shB;   // reuse as scratch (4096 floats)
#pragma unroll
        for (int g = 0; g < GB; g++) red[(g * 64 + n) * 8 + s] = aO[g];
        __syncthreads();
        if (s == 0) {
#pragma unroll
            for (int g = 0; g < GB; g++) {
                float sum = bout[n];
                for (int ss = 0; ss < 8; ss++) sum += red[(g * 64 + n) * 8 + ss];
                out[(size_t)(b0 + g) * 192 + n] = sum;
            }
        }
        __syncthreads();
#pragma unroll
        for (int g = 0; g < GB; g++) red[(g * 64 + n) * 8 + s] = aV[g];
        __syncthreads();
        if (s == 0) {
#pragma unroll
            for (int g = 0; g < GB; g++) {
                float sum = 0.f;
                for (int ss = 0; ss < 8; ss++) sum += red[(g * 64 + n) * 8 + ss];
                out[(size_t)(b0 + g) * 192 + 64 + n] = sum;
            }
        }
    }
}

// ---------------- z_kernel: HMMA Jacobian chain (unchanged, proven) ----------
__device__ __forceinline__ void issue_b128(const __nv_bfloat16* __restrict__ Bg,
                                           int ns, int kc, uint32_t sB, int t) {
#pragma unroll
    for (int i = 0; i < 4; i++) {
        int flat = t + 256 * i;
        int row = flat >> 3, seg = flat & 7;
        CP16(sB + row * B_STRIDE + seg * 16,
             (const char*)(Bg + (size_t)(ns * 128 + row) * HID + kc * 64 + seg * 8));
    }
    CP_COMMIT();
}

__device__ void gemm512(const __nv_bfloat16* __restrict__ Bg,
                        const float* __restrict__ mb,
                        __nv_bfloat16* __restrict__ Ug,
                        uint32_t smu, int t)
{
    const int w = t >> 5, l = t & 31;
    const int wm = w & 3, wn = w >> 2;
    const uint32_t sA = smu + ZP_A;
    const uint32_t aRowB = (wm * 32 + (l & 15)) * A_STRIDE + ((l >> 4) << 4);
    const uint32_t bRowB = ((l & 7) + ((l >> 4) << 3)) * B_STRIDE + (((l >> 3) & 1) << 4);

#pragma unroll 1
    for (int ns = 0; ns < 4; ns++) {
        float c[2][8][4];
#pragma unroll
        for (int mt = 0; mt < 2; mt++)
#pragma unroll
            for (int nt = 0; nt < 8; nt++)
#pragma unroll
                for (int q = 0; q < 4; q++) c[mt][nt][q] = 0.f;

        issue_b128(Bg, ns, 0, smu + ZP_B, t);
        issue_b128(Bg, ns, 1, smu + ZP_B + 18432, t);

#pragma unroll
        for (int kc = 0; kc < 8; kc++) {
            if (kc == 7) { CP_WAIT(0); } else { CP_WAIT(1); }
            __syncthreads();
            uint32_t sB = smu + ZP_B + (kc & 1) * 18432;
#pragma unroll
            for (int ks = 0; ks < 4; ks++) {
                uint32_t a[2][4];
#pragma unroll
                for (int mt = 0; mt < 2; mt++)
                    ldsm4(sA + aRowB + mt * 16 * A_STRIDE + (kc * 64 + ks * 16) * 2,
                          a[mt][0], a[mt][1], a[mt][2], a[mt][3]);
                uint32_t b[8][2];
#pragma unroll
                for (int p = 0; p < 4; p++) {
                    uint32_t addr = sB + (wn * 64 + p * 16) * B_STRIDE + bRowB + ks * 32;
                    uint32_t r0, r1, r2, r3;
                    ldsm4(addr, r0, r1, r2, r3);
                    b[2 * p][0] = r0; b[2 * p][1] = r1;
                    b[2 * p + 1][0] = r2; b[2 * p + 1][1] = r3;
                }
#pragma unroll
                for (int mt = 0; mt < 2; mt++)
#pragma unroll
                    for (int nt = 0; nt < 8; nt++)
                        mma_bf16(c[mt][nt], a[mt], b[nt]);
            }
            __syncthreads();
            if (kc + 2 < 8) issue_b128(Bg, ns, kc + 2, smu + ZP_B + (kc & 1) * 18432, t);
        }

#pragma unroll
        for (int mt = 0; mt < 2; mt++) {
            int r0 = wm * 32 + mt * 16 + (l >> 2);
            const float* mk = mb + ((wm * 32 + mt * 16) >> 6) * HID;
#pragma unroll
            for (int nt = 0; nt < 8; nt++) {
                int col = ns * 128 + wn * 64 + nt * 8 + (l & 3) * 2;
                float m0 = mk[col], m1 = mk[col + 1];
                *(uint32_t*)&Ug[(size_t)r0 * HID + col] =
                    pack_bf16(c[mt][nt][0] * m0, c[mt][nt][1] * m1);
                *(uint32_t*)&Ug[(size_t)(r0 + 8) * HID + col] =
                    pack_bf16(c[mt][nt][2] * m0, c[mt][nt][3] * m1);
            }
        }
    }
    __syncthreads();

#pragma unroll
    for (int i = 0; i < 32; i++) {
        int flat = t + 256 * i;
        int row = flat >> 6, seg = flat & 63;
        CP16(sA + row * A_STRIDE + seg * 16, (const char*)(Ug + (size_t)row * HID + seg * 8));
    }
    CP_COMMIT();
    CP_WAIT(0);
    __syncthreads();
}

__device__ void gemm_final(const __nv_bfloat16* __restrict__ Bg,
                           float* __restrict__ out, int b0, uint32_t smu, int t)
{
    const int w = t >> 5, l = t & 31;
    const uint32_t sA = smu + ZP_A;
    const uint32_t aRowB = (w * 16 + (l & 15)) * A_STRIDE + ((l >> 4) << 4);
    const uint32_t bRowB = ((l & 7) + ((l >> 4) << 3)) * B_STRIDE + (((l >> 3) & 1) << 4);

    float c[8][4];
#pragma unroll
    for (int nt = 0; nt < 8; nt++)
#pragma unroll
        for (int q = 0; q < 4; q++) c[nt][q] = 0.f;

    auto issue64 = [&](int kc, uint32_t sB) {
#pragma unroll
        for (int i = 0; i < 2; i++) {
            int flat = t + 256 * i;
            int row = flat >> 3, seg = flat & 7;
            CP16(sB + row * B_STRIDE + seg * 16,
                 (const char*)(Bg + (size_t)row * HID + kc * 64 + seg * 8));
        }
        CP_COMMIT();
    };

    issue64(0, smu + ZP_B);
    issue64(1, smu + ZP_B + 18432);

#pragma unroll
    for (int kc = 0; kc < 8; kc++) {
        if (kc == 7) { CP_WAIT(0); } else { CP_WAIT(1); }
        __syncthreads();
        uint32_t sB = smu + ZP_B + (kc & 1) * 18432;
#pragma unroll
        for (int ks = 0; ks < 4; ks++) {
            uint32_t a[4];
            ldsm4(sA + aRowB + (kc * 64 + ks * 16) * 2, a[0], a[1], a[2], a[3]);
            uint32_t b[8][2];
#pragma unroll
            for (int p = 0; p < 4; p++) {
                uint32_t addr = sB + (p * 16) * B_STRIDE + bRowB + ks * 32;
                uint32_t r0, r1, r2, r3;
                ldsm4(addr, r0, r1, r2, r3);
                b[2 * p][0] = r0; b[2 * p][1] = r1;
                b[2 * p + 1][0] = r2; b[2 * p + 1][1] = r3;
            }
#pragma unroll
            for (int nt = 0; nt < 8; nt++)
                mma_bf16(c[nt], a, b[nt]);
        }
        __syncthreads();
        if (kc + 2 < 8) issue64(kc + 2, smu + ZP_B + (kc & 1) * 18432);
    }

    float s0 = 0.f, s1 = 0.f;
#pragma unroll
    for (int nt = 0; nt < 8; nt++) {
        s0 += c[nt][0] * c[nt][0] + c[nt][1] * c[nt][1];
        s1 += c[nt][2] * c[nt][2] + c[nt][3] * c[nt][3];
    }
    s0 += __shfl_xor_sync(0xFFFFFFFF, s0, 1);
    s0 += __shfl_xor_sync(0xFFFFFFFF, s0, 2);
    s1 += __shfl_xor_sync(0xFFFFFFFF, s1, 1);
    s1 += __shfl_xor_sync(0xFFFFFFFF, s1, 2);
    if ((l & 3) == 0) {
        int r0 = w * 16 + (l >> 2);
        out[(size_t)(b0 + (r0 >> 6)) * 192 + 128 + (r0 & 63)] = sqrtf(s0);
        int r1 = r0 + 8;
        out[(size_t)(b0 + (r1 >> 6)) * 192 + 128 + (r1 & 63)] = sqrtf(s1);
    }
}

__global__ __launch_bounds__(256) void z_kernel(const float* __restrict__ Wout,
                                                float* __restrict__ out)
{
    extern __shared__ char smz[];
    uint32_t smu = smem_u32(smz);
    int t = threadIdx.x;
    int b0 = blockIdx.x * 2;

    float* msk = (float*)(smz + ZP_MSK);
    for (int i = t; i < 6 * HID; i += 256) {
        int layer = i >> 10, r = i & 1023, item = r >> 9, h = r & 511;
        msk[i] = g_maskB[((size_t)layer * BATCH + b0 + item) * HID + h];
    }
    __syncthreads();

    char* sAc = smz + ZP_A;
    for (int i = t; i < 128 * 256; i += 256) {
        int m = i >> 8, p = i & 255;
        int h = p * 2;
        int item = m >> 6, n = m & 63;
        const float* d3 = msk + (4 + item) * HID;
        *(uint32_t*)(sAc + m * A_STRIDE + h * 2) =
            pack_bf16(Wout[n * HID + h] * d3[h], Wout[n * HID + h + 1] * d3[h + 1]);
    }

    __nv_bfloat16* Ug = g_U + (size_t)blockIdx.x * 128 * HID;
    gemm512(g_WT[1], msk + 2 * HID, Ug, smu, t);
    gemm512(g_WT[0], msk,           Ug, smu, t);
    gemm_final(g_G0T, out, b0, smu, t);
}

// ---------------- launch ----------------------------------------------------
extern "C" void kernel_launch(void* const* d_in, const int* in_sizes, int n_in,
                              void* d_out, int out_size)
{
    const float* x    = (const float*)d_in[0];
    const float* Win  = (const float*)d_in[1];
    const float* bin  = (const float*)d_in[2];
    const float* Wh   = (const float*)d_in[3];
    const float* bh   = (const float*)d_in[4];
    const float* Wout = (const float*)d_in[5];
    const float* bout = (const float*)d_in[6];
    float* out = (float*)d_out;

    int B = in_sizes[0] / 192;   // 4096

    const int fwd_smem = (GB * (3 * NDIM + 3 * HID)) * sizeof(float);   // 55296
    cudaFuncSetAttribute(fwd_kernel, cudaFuncAttributeMaxDynamicSharedMemorySize, fwd_smem);
    cudaFuncSetAttribute(z_kernel,   cudaFuncAttributeMaxDynamicSharedMemorySize, Z_SMEM);

    prep_g0<<<HID, NDIM>>>(Wh, Win);
    prep_wt<<<1024, 128>>>(Wh);
    prep_g0t<<<NDIM, HID>>>();
    fwd_kernel<<<B / GB, 512, fwd_smem>>>(x, Win, bin, Wh, bh, Wout, bout, out);
    z_kernel<<<B / 2, 256, Z_SMEM>>>(Wout, out);
}

// round 11
// speedup vs baseline: 4.8241x; 1.2244x over previous
#include <cuda_runtime.h>
#include <cuda_bf16.h>
#include <math.h>
#include <stdint.h>

#define BATCH 4096
#define NDIM  64
#define HID   512
#define GB    8

// ---------------- device globals (static: allocation APIs are banned) -------
__device__ float g_G0[HID * NDIM];                          // G0 = Wh0 @ Win (fp32)
__device__ float g_maskB[3 * BATCH * HID];                  // zero-branch masks
__device__ __align__(16) __nv_bfloat16 g_WT[2][HID * HID];  // Wh1^T, Wh2^T  [n][k]
__device__ __align__(16) __nv_bfloat16 g_G0T[NDIM * HID];   // G0^T [d][h]
__device__ __align__(16) __nv_bfloat16 g_U[(size_t)(BATCH / 2) * 128 * HID]; // U staging

// ---------------- SMEM map for z_kernel (bytes) -----------------------------
#define ZP_MSK   0                       // 6*512 fp32 = 12288
#define ZP_A     12288                   // 128 rows * 520 bf16 = 133120
#define ZP_B     145408                  // 2 * (128 * 144B) = 36864
#define Z_SMEM   182272
#define A_STRIDE 1040                    // bytes per A row (520 bf16)
#define B_STRIDE 144                     // bytes per B row (72 bf16)

// ---------------- asm helpers ------------------------------------------------
__device__ __forceinline__ uint32_t smem_u32(const void* p) {
    uint32_t a;
    asm("{ .reg .u64 t; cvta.to.shared.u64 t, %1; cvt.u32.u64 %0, t; }" : "=r"(a) : "l"(p));
    return a;
}
#define CP16(dst, src)  asm volatile("cp.async.cg.shared.global [%0], [%1], 16;" :: "r"(dst), "l"(src))
#define CP_COMMIT()     asm volatile("cp.async.commit_group;" ::: "memory")
#define CP_WAIT(n)      asm volatile("cp.async.wait_group %0;" :: "n"(n) : "memory")

__device__ __forceinline__ void ldsm4(uint32_t addr, uint32_t& r0, uint32_t& r1,
                                      uint32_t& r2, uint32_t& r3) {
    asm volatile("ldmatrix.sync.aligned.m8n8.x4.shared.b16 {%0,%1,%2,%3}, [%4];"
        : "=r"(r0), "=r"(r1), "=r"(r2), "=r"(r3) : "r"(addr));
}
__device__ __forceinline__ void mma_bf16(float* c, const uint32_t* a, const uint32_t* b) {
    asm volatile("mma.sync.aligned.m16n8k16.row.col.f32.bf16.bf16.f32 "
        "{%0,%1,%2,%3}, {%4,%5,%6,%7}, {%8,%9}, {%0,%1,%2,%3};"
        : "+f"(c[0]), "+f"(c[1]), "+f"(c[2]), "+f"(c[3])
        : "r"(a[0]), "r"(a[1]), "r"(a[2]), "r"(a[3]), "r"(b[0]), "r"(b[1]));
}
__device__ __forceinline__ uint32_t pack_bf16(float lo, float hi) {
    uint32_t pk;
    asm("cvt.rn.bf16x2.f32 %0, %1, %2;" : "=r"(pk) : "f"(hi), "f"(lo));
    return pk;
}

// ---------------- prep kernels ----------------------------------------------
__global__ void prep_g0(const float* __restrict__ Wh, const float* __restrict__ Win) {
    int i = blockIdx.x, d = threadIdx.x;
    float acc = 0.f;
    for (int j = 0; j < HID; j++) acc += Wh[i * HID + j] * Win[j * NDIM + d];
    g_G0[i * NDIM + d] = acc;
}
__global__ void prep_wt(const float* __restrict__ Wh) {
    int li = blockIdx.x >> 9, n = blockIdx.x & 511;
    const float* base = Wh + (size_t)(li + 1) * HID * HID;
    __nv_bfloat16* dst = g_WT[li] + (size_t)n * HID;
    for (int k = threadIdx.x; k < HID; k += 128)
        dst[k] = __float2bfloat16(base[(size_t)k * HID + n]);
}
__global__ void prep_g0t() {
    int d = blockIdx.x, h = threadIdx.x;
    g_G0T[d * HID + h] = __float2bfloat16(g_G0[h * NDIM + d]);
}

// ---------------- forward: fp32 scalar, 2 rows/thread, [h][g] layout ---------
// Per-row summation order identical to the proven kernel -> bit-identical out.
union F8 { float4 v[2]; float f[GB]; };

__global__ __launch_bounds__(256) void fwd_kernel(
    const float* __restrict__ x,
    const float* __restrict__ Win, const float* __restrict__ bin,
    const float* __restrict__ Wh,  const float* __restrict__ bh,
    const float* __restrict__ Wout, const float* __restrict__ bout,
    float* __restrict__ out)
{
    extern __shared__ float sm[];
    float* sxA = sm;                    // [64][8]
    float* sxZ = sxA + NDIM * GB;       // [64][8]
    float* sxD = sxZ + NDIM * GB;       // [64][8]
    float* shA = sxD + NDIM * GB;       // [512][8]
    float* shB = shA + HID * GB;        // [512][8]
    float* sv  = shB + HID * GB;        // [512][8]

    int t  = threadIdx.x;               // 0..255
    int t1 = t + 256;                   // second row
    int b0 = blockIdx.x * GB;

    for (int i = t; i < GB * 192; i += 256) {
        int g = i / 192, c = i % 192;
        float v = x[(b0 + g) * 192 + c];
        if (c < 64)       sxA[c * GB + g] = v;
        else if (c < 128) sxD[(c - 64) * GB + g] = v;
        else              sxZ[(c - 128) * GB + g] = v;
    }
    __syncthreads();

    // h0 (no relu) both branches + v0 = G0 @ xtdot  (2 rows per thread)
    {
        float aA[2][GB], aB[2][GB], aV[2][GB];
        float bi0 = bin[t], bi1 = bin[t1];
#pragma unroll
        for (int g = 0; g < GB; g++) {
            aA[0][g] = bi0; aB[0][g] = bi0; aV[0][g] = 0.f;
            aA[1][g] = bi1; aB[1][g] = bi1; aV[1][g] = 0.f;
        }
        for (int d = 0; d < NDIM; d++) {
            float w0 = Win[t  * NDIM + d], w1 = Win[t1 * NDIM + d];
            float p0 = g_G0[t * NDIM + d], p1 = g_G0[t1 * NDIM + d];
            F8 xa, xz, xd;
            xa.v[0] = *(const float4*)&sxA[d * GB]; xa.v[1] = *(const float4*)&sxA[d * GB + 4];
            xz.v[0] = *(const float4*)&sxZ[d * GB]; xz.v[1] = *(const float4*)&sxZ[d * GB + 4];
            xd.v[0] = *(const float4*)&sxD[d * GB]; xd.v[1] = *(const float4*)&sxD[d * GB + 4];
#pragma unroll
            for (int g = 0; g < GB; g++) {
                aA[0][g] += w0 * xa.f[g];  aA[1][g] += w1 * xa.f[g];
                aB[0][g] += w0 * xz.f[g];  aB[1][g] += w1 * xz.f[g];
                aV[0][g] += p0 * xd.f[g];  aV[1][g] += p1 * xd.f[g];
            }
        }
#pragma unroll
        for (int g = 0; g < GB; g++) {
            shA[t  * GB + g] = aA[0][g]; shA[t1 * GB + g] = aA[1][g];
            shB[t  * GB + g] = aB[0][g]; shB[t1 * GB + g] = aB[1][g];
            sv [t  * GB + g] = aV[0][g]; sv [t1 * GB + g] = aV[1][g];
        }
    }
    __syncthreads();

#pragma unroll 1
    for (int l = 0; l < 3; l++) {
        const float* W = Wh + (size_t)l * HID * HID;
        const float4* Wr0 = (const float4*)(W + (size_t)t  * HID);
        const float4* Wr1 = (const float4*)(W + (size_t)t1 * HID);
        float bias0 = bh[l * HID + t], bias1 = bh[l * HID + t1];

        // ---- pass 1: h_{l+1} = relu(W h_l + b); v = W v (layers 1,2) ----
        float aA[2][GB], aB[2][GB], aV[2][GB];
#pragma unroll
        for (int g = 0; g < GB; g++) {
            aA[0][g] = bias0; aB[0][g] = bias0; aV[0][g] = 0.f;
            aA[1][g] = bias1; aB[1][g] = bias1; aV[1][g] = 0.f;
        }
#pragma unroll 2
        for (int k4 = 0; k4 < HID / 4; k4++) {
            float4 w40 = Wr0[k4], w41 = Wr1[k4];
#pragma unroll
            for (int q = 0; q < 4; q++) {
                float w0 = (&w40.x)[q], w1 = (&w41.x)[q];
                int k = k4 * 4 + q;
                F8 ha, hb, vv;
                ha.v[0] = *(const float4*)&shA[k * GB]; ha.v[1] = *(const float4*)&shA[k * GB + 4];
                hb.v[0] = *(const float4*)&shB[k * GB]; hb.v[1] = *(const float4*)&shB[k * GB + 4];
                if (l > 0) {
                    vv.v[0] = *(const float4*)&sv[k * GB]; vv.v[1] = *(const float4*)&sv[k * GB + 4];
                }
#pragma unroll
                for (int g = 0; g < GB; g++) {
                    aA[0][g] += w0 * ha.f[g];  aA[1][g] += w1 * ha.f[g];
                    aB[0][g] += w0 * hb.f[g];  aB[1][g] += w1 * hb.f[g];
                    if (l > 0) { aV[0][g] += w0 * vv.f[g]; aV[1][g] += w1 * vv.f[g]; }
                }
            }
        }
        __syncthreads();   // all reads done before overwriting
#pragma unroll
        for (int g = 0; g < GB; g++) {
            shA[t  * GB + g] = fmaxf(aA[0][g], 0.f);
            shA[t1 * GB + g] = fmaxf(aA[1][g], 0.f);
            shB[t  * GB + g] = fmaxf(aB[0][g], 0.f);
            shB[t1 * GB + g] = fmaxf(aB[1][g], 0.f);
            if (l > 0) { sv[t * GB + g] = aV[0][g]; sv[t1 * GB + g] = aV[1][g]; }
        }
        __syncthreads();

        // ---- pass 2: delta^{(l)} = (W h_{l+1} + b > 0)  (bug-faithful mask)
#pragma unroll
        for (int g = 0; g < GB; g++) {
            aA[0][g] = bias0; aB[0][g] = bias0;
            aA[1][g] = bias1; aB[1][g] = bias1;
        }
#pragma unroll 2
        for (int k4 = 0; k4 < HID / 4; k4++) {
            float4 w40 = Wr0[k4], w41 = Wr1[k4];
#pragma unroll
            for (int q = 0; q < 4; q++) {
                float w0 = (&w40.x)[q], w1 = (&w41.x)[q];
                int k = k4 * 4 + q;
                F8 ha, hb;
                ha.v[0] = *(const float4*)&shA[k * GB]; ha.v[1] = *(const float4*)&shA[k * GB + 4];
                hb.v[0] = *(const float4*)&shB[k * GB]; hb.v[1] = *(const float4*)&shB[k * GB + 4];
#pragma unroll
                for (int g = 0; g < GB; g++) {
                    aA[0][g] += w0 * ha.f[g];  aA[1][g] += w1 * ha.f[g];
                    aB[0][g] += w0 * hb.f[g];  aB[1][g] += w1 * hb.f[g];
                }
            }
        }
#pragma unroll
        for (int g = 0; g < GB; g++) {
            float dA0 = aA[0][g] > 0.f ? 1.f : 0.f;
            float dA1 = aA[1][g] > 0.f ? 1.f : 0.f;
            sv[t  * GB + g] *= dA0;
            sv[t1 * GB + g] *= dA1;
            g_maskB[((size_t)l * BATCH + (b0 + g)) * HID + t]  = aB[0][g] > 0.f ? 1.f : 0.f;
            g_maskB[((size_t)l * BATCH + (b0 + g)) * HID + t1] = aB[1][g] > 0.f ? 1.f : 0.f;
        }
        __syncthreads();
    }

    // ---- final: h_out = Wout h3 + bout ; h_dot = Wout v -------------------
    // thread t -> pairs (n,s) = (t>>3, t&7) and ((t+256)>>3, t&7); same per-pair order
    {
        float aO[2][GB], aV[2][GB];
#pragma unroll
        for (int g = 0; g < GB; g++) {
            aO[0][g] = 0.f; aV[0][g] = 0.f;
            aO[1][g] = 0.f; aV[1][g] = 0.f;
        }
        int n0 = t >> 3, s = t & 7;
        int n1 = n0 + 32;
        for (int h = s * 64; h < s * 64 + 64; h++) {
            float w0 = Wout[n0 * HID + h], w1 = Wout[n1 * HID + h];
            F8 ha, vv;
            ha.v[0] = *(const float4*)&shA[h * GB]; ha.v[1] = *(const float4*)&shA[h * GB + 4];
            vv.v[0] = *(const float4*)&sv [h * GB]; vv.v[1] = *(const float4*)&sv [h * GB + 4];
#pragma unroll
            for (int g = 0; g < GB; g++) {
                aO[0][g] += w0 * ha.f[g];  aO[1][g] += w1 * ha.f[g];
                aV[0][g] += w0 * vv.f[g];  aV[1][g] += w1 * vv.f[g];
            }
        }
        float* red = shB;   // reuse as scratch (4096 floats)
#pragma unroll
        for (int g = 0; g < GB; g++) {
            red[(g * 64 + n0) * 8 + s] = aO[0][g];
            red[(g * 64 + n1) * 8 + s] = aO[1][g];
        }
        __syncthreads();
        if (s == 0) {
#pragma unroll
            for (int g = 0; g < GB; g++) {
                float s0 = bout[n0], s1 = bout[n1];
                for (int ss = 0; ss < 8; ss++) {
                    s0 += red[(g * 64 + n0) * 8 + ss];
                    s1 += red[(g * 64 + n1) * 8 + ss];
                }
                out[(size_t)(b0 + g) * 192 + n0] = s0;
                out[(size_t)(b0 + g) * 192 + n1] = s1;
            }
        }
        __syncthreads();
#pragma unroll
        for (int g = 0; g < GB; g++) {
            red[(g * 64 + n0) * 8 + s] = aV[0][g];
            red[(g * 64 + n1) * 8 + s] = aV[1][g];
        }
        __syncthreads();
        if (s == 0) {
#pragma unroll
            for (int g = 0; g < GB; g++) {
                float s0 = 0.f, s1 = 0.f;
                for (int ss = 0; ss < 8; ss++) {
                    s0 += red[(g * 64 + n0) * 8 + ss];
                    s1 += red[(g * 64 + n1) * 8 + ss];
                }
                out[(size_t)(b0 + g) * 192 + 64 + n0] = s0;
                out[(size_t)(b0 + g) * 192 + 64 + n1] = s1;
            }
        }
    }
}

// ---------------- z_kernel: HMMA Jacobian chain (unchanged, proven) ----------
__device__ __forceinline__ void issue_b128(const __nv_bfloat16* __restrict__ Bg,
                                           int ns, int kc, uint32_t sB, int t) {
#pragma unroll
    for (int i = 0; i < 4; i++) {
        int flat = t + 256 * i;
        int row = flat >> 3, seg = flat & 7;
        CP16(sB + row * B_STRIDE + seg * 16,
             (const char*)(Bg + (size_t)(ns * 128 + row) * HID + kc * 64 + seg * 8));
    }
    CP_COMMIT();
}

__device__ void gemm512(const __nv_bfloat16* __restrict__ Bg,
                        const float* __restrict__ mb,
                        __nv_bfloat16* __restrict__ Ug,
                        uint32_t smu, int t)
{
    const int w = t >> 5, l = t & 31;
    const int wm = w & 3, wn = w >> 2;
    const uint32_t sA = smu + ZP_A;
    const uint32_t aRowB = (wm * 32 + (l & 15)) * A_STRIDE + ((l >> 4) << 4);
    const uint32_t bRowB = ((l & 7) + ((l >> 4) << 3)) * B_STRIDE + (((l >> 3) & 1) << 4);

#pragma unroll 1
    for (int ns = 0; ns < 4; ns++) {
        float c[2][8][4];
#pragma unroll
        for (int mt = 0; mt < 2; mt++)
#pragma unroll
            for (int nt = 0; nt < 8; nt++)
#pragma unroll
                for (int q = 0; q < 4; q++) c[mt][nt][q] = 0.f;

        issue_b128(Bg, ns, 0, smu + ZP_B, t);
        issue_b128(Bg, ns, 1, smu + ZP_B + 18432, t);

#pragma unroll
        for (int kc = 0; kc < 8; kc++) {
            if (kc == 7) { CP_WAIT(0); } else { CP_WAIT(1); }
            __syncthreads();
            uint32_t sB = smu + ZP_B + (kc & 1) * 18432;
#pragma unroll
            for (int ks = 0; ks < 4; ks++) {
                uint32_t a[2][4];
#pragma unroll
                for (int mt = 0; mt < 2; mt++)
                    ldsm4(sA + aRowB + mt * 16 * A_STRIDE + (kc * 64 + ks * 16) * 2,
                          a[mt][0], a[mt][1], a[mt][2], a[mt][3]);
                uint32_t b[8][2];
#pragma unroll
                for (int p = 0; p < 4; p++) {
                    uint32_t addr = sB + (wn * 64 + p * 16) * B_STRIDE + bRowB + ks * 32;
                    uint32_t r0, r1, r2, r3;
                    ldsm4(addr, r0, r1, r2, r3);
                    b[2 * p][0] = r0; b[2 * p][1] = r1;
                    b[2 * p + 1][0] = r2; b[2 * p + 1][1] = r3;
                }
#pragma unroll
                for (int mt = 0; mt < 2; mt++)
#pragma unroll
                    for (int nt = 0; nt < 8; nt++)
                        mma_bf16(c[mt][nt], a[mt], b[nt]);
            }
            __syncthreads();
            if (kc + 2 < 8) issue_b128(Bg, ns, kc + 2, smu + ZP_B + (kc & 1) * 18432, t);
        }

#pragma unroll
        for (int mt = 0; mt < 2; mt++) {
            int r0 = wm * 32 + mt * 16 + (l >> 2);
            const float* mk = mb + ((wm * 32 + mt * 16) >> 6) * HID;
#pragma unroll
            for (int nt = 0; nt < 8; nt++) {
                int col = ns * 128 + wn * 64 + nt * 8 + (l & 3) * 2;
                float m0 = mk[col], m1 = mk[col + 1];
                *(uint32_t*)&Ug[(size_t)r0 * HID + col] =
                    pack_bf16(c[mt][nt][0] * m0, c[mt][nt][1] * m1);
                *(uint32_t*)&Ug[(size_t)(r0 + 8) * HID + col] =
                    pack_bf16(c[mt][nt][2] * m0, c[mt][nt][3] * m1);
            }
        }
    }
    __syncthreads();

#pragma unroll
    for (int i = 0; i < 32; i++) {
        int flat = t + 256 * i;
        int row = flat >> 6, seg = flat & 63;
        CP16(sA + row * A_STRIDE + seg * 16, (const char*)(Ug + (size_t)row * HID + seg * 8));
    }
    CP_COMMIT();
    CP_WAIT(0);
    __syncthreads();
}

__device__ void gemm_final(const __nv_bfloat16* __restrict__ Bg,
                           float* __restrict__ out, int b0, uint32_t smu, int t)
{
    const int w = t >> 5, l = t & 31;
    const uint32_t sA = smu + ZP_A;
    const uint32_t aRowB = (w * 16 + (l & 15)) * A_STRIDE + ((l >> 4) << 4);
    const uint32_t bRowB = ((l & 7) + ((l >> 4) << 3)) * B_STRIDE + (((l >> 3) & 1) << 4);

    float c[8][4];
#pragma unroll
    for (int nt = 0; nt < 8; nt++)
#pragma unroll
        for (int q = 0; q < 4; q++) c[nt][q] = 0.f;

    auto issue64 = [&](int kc, uint32_t sB) {
#pragma unroll
        for (int i = 0; i < 2; i++) {
            int flat = t + 256 * i;
            int row = flat >> 3, seg = flat & 7;
            CP16(sB + row * B_STRIDE + seg * 16,
                 (const char*)(Bg + (size_t)row * HID + kc * 64 + seg * 8));
        }
        CP_COMMIT();
    };

    issue64(0, smu + ZP_B);
    issue64(1, smu + ZP_B + 18432);

#pragma unroll
    for (int kc = 0; kc < 8; kc++) {
        if (kc == 7) { CP_WAIT(0); } else { CP_WAIT(1); }
        __syncthreads();
        uint32_t sB = smu + ZP_B + (kc & 1) * 18432;
#pragma unroll
        for (int ks = 0; ks < 4; ks++) {
            uint32_t a[4];
            ldsm4(sA + aRowB + (kc * 64 + ks * 16) * 2, a[0], a[1], a[2], a[3]);
            uint32_t b[8][2];
#pragma unroll
            for (int p = 0; p < 4; p++) {
                uint32_t addr = sB + (p * 16) * B_STRIDE + bRowB + ks * 32;
                uint32_t r0, r1, r2, r3;
                ldsm4(addr, r0, r1, r2, r3);
                b[2 * p][0] = r0; b[2 * p][1] = r1;
                b[2 * p + 1][0] = r2; b[2 * p + 1][1] = r3;
            }
#pragma unroll
            for (int nt = 0; nt < 8; nt++)
                mma_bf16(c[nt], a, b[nt]);
        }
        __syncthreads();
        if (kc + 2 < 8) issue64(kc + 2, smu + ZP_B + (kc & 1) * 18432);
    }

    float s0 = 0.f, s1 = 0.f;
#pragma unroll
    for (int nt = 0; nt < 8; nt++) {
        s0 += c[nt][0] * c[nt][0] + c[nt][1] * c[nt][1];
        s1 += c[nt][2] * c[nt][2] + c[nt][3] * c[nt][3];
    }
    s0 += __shfl_xor_sync(0xFFFFFFFF, s0, 1);
    s0 += __shfl_xor_sync(0xFFFFFFFF, s0, 2);
    s1 += __shfl_xor_sync(0xFFFFFFFF, s1, 1);
    s1 += __shfl_xor_sync(0xFFFFFFFF, s1, 2);
    if ((l & 3) == 0) {
        int r0 = w * 16 + (l >> 2);
        out[(size_t)(b0 + (r0 >> 6)) * 192 + 128 + (r0 & 63)] = sqrtf(s0);
        int r1 = r0 + 8;
        out[(size_t)(b0 + (r1 >> 6)) * 192 + 128 + (r1 & 63)] = sqrtf(s1);
    }
}

__global__ __launch_bounds__(256) void z_kernel(const float* __restrict__ Wout,
                                                float* __restrict__ out)
{
    extern __shared__ char smz[];
    uint32_t smu = smem_u32(smz);
    int t = threadIdx.x;
    int b0 = blockIdx.x * 2;

    float* msk = (float*)(smz + ZP_MSK);
    for (int i = t; i < 6 * HID; i += 256) {
        int layer = i >> 10, r = i & 1023, item = r >> 9, h = r & 511;
        msk[i] = g_maskB[((size_t)layer * BATCH + b0 + item) * HID + h];
    }
    __syncthreads();

    char* sAc = smz + ZP_A;
    for (int i = t; i < 128 * 256; i += 256) {
        int m = i >> 8, p = i & 255;
        int h = p * 2;
        int item = m >> 6, n = m & 63;
        const float* d3 = msk + (4 + item) * HID;
        *(uint32_t*)(sAc + m * A_STRIDE + h * 2) =
            pack_bf16(Wout[n * HID + h] * d3[h], Wout[n * HID + h + 1] * d3[h + 1]);
    }

    __nv_bfloat16* Ug = g_U + (size_t)blockIdx.x * 128 * HID;
    gemm512(g_WT[1], msk + 2 * HID, Ug, smu, t);
    gemm512(g_WT[0], msk,           Ug, smu, t);
    gemm_final(g_G0T, out, b0, smu, t);
}

// ---------------- launch ----------------------------------------------------
extern "C" void kernel_launch(void* const* d_in, const int* in_sizes, int n_in,
                              void* d_out, int out_size)
{
    const float* x    = (const float*)d_in[0];
    const float* Win  = (const float*)d_in[1];
    const float* bin  = (const float*)d_in[2];
    const float* Wh   = (const float*)d_in[3];
    const float* bh   = (const float*)d_in[4];
    const float* Wout = (const float*)d_in[5];
    const float* bout = (const float*)d_in[6];
    float* out = (float*)d_out;

    int B = in_sizes[0] / 192;   // 4096

    const int fwd_smem = (GB * (3 * NDIM + 3 * HID)) * sizeof(float);   // 55296
    cudaFuncSetAttribute(fwd_kernel, cudaFuncAttributeMaxDynamicSharedMemorySize, fwd_smem);
    cudaFuncSetAttribute(z_kernel,   cudaFuncAttributeMaxDynamicSharedMemorySize, Z_SMEM);

    prep_g0<<<HID, NDIM>>>(Wh, Win);
    prep_wt<<<1024, 128>>>(Wh);
    prep_g0t<<<NDIM, HID>>>();
    fwd_kernel<<<B / GB, 256, fwd_smem>>>(x, Win, bin, Wh, bh, Wout, bout, out);
    z_kernel<<<B / 2, 256, Z_SMEM>>>(Wout, out);
}

// round 12
// speedup vs baseline: 6.6702x; 1.3827x over previous
#include <cuda_runtime.h>
#include <cuda_bf16.h>
#include <math.h>
#include <stdint.h>

#define BATCH 4096
#define NDIM  64
#define HID   512
#define GB    8

// ---------------- device globals (static: allocation APIs are banned) -------
__device__ float g_G0[HID * NDIM];                          // G0 = Wh0 @ Win (fp32)
__device__ float g_maskB[3 * BATCH * HID];                  // zero-branch masks
__device__ __align__(16) __nv_bfloat16 g_WT[2][HID * HID];  // Wh1^T, Wh2^T  [n][k]
__device__ __align__(16) __nv_bfloat16 g_G0T[NDIM * HID];   // G0^T [d][h]
__device__ __align__(16) __nv_bfloat16 g_U[(size_t)(BATCH / 2) * 128 * HID]; // U staging
// coalesced packed weights for fwd: [k][t] = (W[t][k], W[t+256][k])
__device__ __align__(16) float2 g_WP[3 * HID * 256];
__device__ __align__(16) float2 g_WinP[NDIM * 256];
__device__ __align__(16) float2 g_G0P[NDIM * 256];
__device__ __align__(16) float  g_WoutT[HID * NDIM];        // [h][n]

// ---------------- SMEM map for z_kernel (bytes) -----------------------------
#define ZP_MSK   0                       // 6*512 fp32 = 12288
#define ZP_A     12288                   // 128 rows * 520 bf16 = 133120
#define ZP_B     145408                  // 2 * (128 * 144B) = 36864
#define Z_SMEM   182272
#define A_STRIDE 1040                    // bytes per A row (520 bf16)
#define B_STRIDE 144                     // bytes per B row (72 bf16)

// ---------------- asm helpers ------------------------------------------------
__device__ __forceinline__ uint32_t smem_u32(const void* p) {
    uint32_t a;
    asm("{ .reg .u64 t; cvta.to.shared.u64 t, %1; cvt.u32.u64 %0, t; }" : "=r"(a) : "l"(p));
    return a;
}
#define CP16(dst, src)  asm volatile("cp.async.cg.shared.global [%0], [%1], 16;" :: "r"(dst), "l"(src))
#define CP_COMMIT()     asm volatile("cp.async.commit_group;" ::: "memory")
#define CP_WAIT(n)      asm volatile("cp.async.wait_group %0;" :: "n"(n) : "memory")

__device__ __forceinline__ void ldsm4(uint32_t addr, uint32_t& r0, uint32_t& r1,
                                      uint32_t& r2, uint32_t& r3) {
    asm volatile("ldmatrix.sync.aligned.m8n8.x4.shared.b16 {%0,%1,%2,%3}, [%4];"
        : "=r"(r0), "=r"(r1), "=r"(r2), "=r"(r3) : "r"(addr));
}
__device__ __forceinline__ void mma_bf16(float* c, const uint32_t* a, const uint32_t* b) {
    asm volatile("mma.sync.aligned.m16n8k16.row.col.f32.bf16.bf16.f32 "
        "{%0,%1,%2,%3}, {%4,%5,%6,%7}, {%8,%9}, {%0,%1,%2,%3};"
        : "+f"(c[0]), "+f"(c[1]), "+f"(c[2]), "+f"(c[3])
        : "r"(a[0]), "r"(a[1]), "r"(a[2]), "r"(a[3]), "r"(b[0]), "r"(b[1]));
}
__device__ __forceinline__ uint32_t pack_bf16(float lo, float hi) {
    uint32_t pk;
    asm("cvt.rn.bf16x2.f32 %0, %1, %2;" : "=r"(pk) : "f"(hi), "f"(lo));
    return pk;
}

// ---------------- prep kernels ----------------------------------------------
__global__ void prep_g0(const float* __restrict__ Wh, const float* __restrict__ Win) {
    int i = blockIdx.x, d = threadIdx.x;
    float acc = 0.f;
    for (int j = 0; j < HID; j++) acc += Wh[i * HID + j] * Win[j * NDIM + d];
    g_G0[i * NDIM + d] = acc;
}
__global__ void prep_wt(const float* __restrict__ Wh) {
    int li = blockIdx.x >> 9, n = blockIdx.x & 511;
    const float* base = Wh + (size_t)(li + 1) * HID * HID;
    __nv_bfloat16* dst = g_WT[li] + (size_t)n * HID;
    for (int k = threadIdx.x; k < HID; k += 128)
        dst[k] = __float2bfloat16(base[(size_t)k * HID + n]);
}
__global__ void prep_g0t() {
    int d = blockIdx.x, h = threadIdx.x;
    g_G0T[d * HID + h] = __float2bfloat16(g_G0[h * NDIM + d]);
}
// pack Wh rows (t, t+256) per k, coalesced reads
__global__ void prep_wp(const float* __restrict__ Wh) {
    int l = blockIdx.x >> 8, tt = blockIdx.x & 255;
    int k = threadIdx.x;                 // 0..511
    const float* base = Wh + (size_t)l * HID * HID;
    float w0 = base[(size_t)tt * HID + k];
    float w1 = base[(size_t)(tt + 256) * HID + k];
    g_WP[((size_t)l * HID + k) * 256 + tt] = make_float2(w0, w1);
}
__global__ void prep_winp(const float* __restrict__ Win) {
    int tt = blockIdx.x;                 // 0..255
    int d = threadIdx.x;                 // 0..63
    g_WinP[d * 256 + tt] = make_float2(Win[tt * NDIM + d], Win[(tt + 256) * NDIM + d]);
    g_G0P [d * 256 + tt] = make_float2(g_G0[tt * NDIM + d], g_G0[(tt + 256) * NDIM + d]);
}
__global__ void prep_woutt(const float* __restrict__ Wout) {
    int h = blockIdx.x, n = threadIdx.x;
    g_WoutT[h * NDIM + n] = Wout[n * HID + h];
}

// ---------------- forward: fp32 scalar, 2 rows/thread, coalesced weights -----
// Per-row summation order identical to the proven kernel -> bit-identical out.
union F8 { float4 v[2]; float f[GB]; };

__global__ __launch_bounds__(256) void fwd_kernel(
    const float* __restrict__ x,
    const float* __restrict__ bin, const float* __restrict__ bh,
    const float* __restrict__ bout,
    float* __restrict__ out)
{
    extern __shared__ float sm[];
    float* sxA = sm;                    // [64][8]
    float* sxZ = sxA + NDIM * GB;       // [64][8]
    float* sxD = sxZ + NDIM * GB;       // [64][8]
    float* shA = sxD + NDIM * GB;       // [512][8]
    float* shB = shA + HID * GB;        // [512][8]
    float* sv  = shB + HID * GB;        // [512][8]

    int t  = threadIdx.x;               // 0..255
    int t1 = t + 256;                   // second row
    int b0 = blockIdx.x * GB;

    for (int i = t; i < GB * 192; i += 256) {
        int g = i / 192, c = i % 192;
        float v = x[(b0 + g) * 192 + c];
        if (c < 64)       sxA[c * GB + g] = v;
        else if (c < 128) sxD[(c - 64) * GB + g] = v;
        else              sxZ[(c - 128) * GB + g] = v;
    }
    __syncthreads();

    // h0 (no relu) both branches + v0 = G0 @ xtdot  (2 rows per thread)
    {
        float aA[2][GB], aB[2][GB], aV[2][GB];
        float bi0 = bin[t], bi1 = bin[t1];
#pragma unroll
        for (int g = 0; g < GB; g++) {
            aA[0][g] = bi0; aB[0][g] = bi0; aV[0][g] = 0.f;
            aA[1][g] = bi1; aB[1][g] = bi1; aV[1][g] = 0.f;
        }
#pragma unroll 4
        for (int d = 0; d < NDIM; d++) {
            float2 wp = g_WinP[d * 256 + t];
            float2 gp = g_G0P [d * 256 + t];
            F8 xa, xz, xd;
            xa.v[0] = *(const float4*)&sxA[d * GB]; xa.v[1] = *(const float4*)&sxA[d * GB + 4];
            xz.v[0] = *(const float4*)&sxZ[d * GB]; xz.v[1] = *(const float4*)&sxZ[d * GB + 4];
            xd.v[0] = *(const float4*)&sxD[d * GB]; xd.v[1] = *(const float4*)&sxD[d * GB + 4];
#pragma unroll
            for (int g = 0; g < GB; g++) {
                aA[0][g] += wp.x * xa.f[g];  aA[1][g] += wp.y * xa.f[g];
                aB[0][g] += wp.x * xz.f[g];  aB[1][g] += wp.y * xz.f[g];
                aV[0][g] += gp.x * xd.f[g];  aV[1][g] += gp.y * xd.f[g];
            }
        }
#pragma unroll
        for (int g = 0; g < GB; g++) {
            shA[t  * GB + g] = aA[0][g]; shA[t1 * GB + g] = aA[1][g];
            shB[t  * GB + g] = aB[0][g]; shB[t1 * GB + g] = aB[1][g];
            sv [t  * GB + g] = aV[0][g]; sv [t1 * GB + g] = aV[1][g];
        }
    }
    __syncthreads();

#pragma unroll 1
    for (int l = 0; l < 3; l++) {
        const float2* wpL = g_WP + (size_t)l * HID * 256;
        float bias0 = bh[l * HID + t], bias1 = bh[l * HID + t1];

        // ---- pass 1: h_{l+1} = relu(W h_l + b); v = W v (layers 1,2) ----
        float aA[2][GB], aB[2][GB], aV[2][GB];
#pragma unroll
        for (int g = 0; g < GB; g++) {
            aA[0][g] = bias0; aB[0][g] = bias0; aV[0][g] = 0.f;
            aA[1][g] = bias1; aB[1][g] = bias1; aV[1][g] = 0.f;
        }
#pragma unroll 4
        for (int k = 0; k < HID; k++) {
            float2 wp = wpL[k * 256 + t];
            F8 ha, hb, vv;
            ha.v[0] = *(const float4*)&shA[k * GB]; ha.v[1] = *(const float4*)&shA[k * GB + 4];
            hb.v[0] = *(const float4*)&shB[k * GB]; hb.v[1] = *(const float4*)&shB[k * GB + 4];
            if (l > 0) {
                vv.v[0] = *(const float4*)&sv[k * GB]; vv.v[1] = *(const float4*)&sv[k * GB + 4];
            }
#pragma unroll
            for (int g = 0; g < GB; g++) {
                aA[0][g] += wp.x * ha.f[g];  aA[1][g] += wp.y * ha.f[g];
                aB[0][g] += wp.x * hb.f[g];  aB[1][g] += wp.y * hb.f[g];
                if (l > 0) { aV[0][g] += wp.x * vv.f[g]; aV[1][g] += wp.y * vv.f[g]; }
            }
        }
        __syncthreads();   // all reads done before overwriting
#pragma unroll
        for (int g = 0; g < GB; g++) {
            shA[t  * GB + g] = fmaxf(aA[0][g], 0.f);
            shA[t1 * GB + g] = fmaxf(aA[1][g], 0.f);
            shB[t  * GB + g] = fmaxf(aB[0][g], 0.f);
            shB[t1 * GB + g] = fmaxf(aB[1][g], 0.f);
            if (l > 0) { sv[t * GB + g] = aV[0][g]; sv[t1 * GB + g] = aV[1][g]; }
        }
        __syncthreads();

        // ---- pass 2: delta^{(l)} = (W h_{l+1} + b > 0)  (bug-faithful mask)
#pragma unroll
        for (int g = 0; g < GB; g++) {
            aA[0][g] = bias0; aB[0][g] = bias0;
            aA[1][g] = bias1; aB[1][g] = bias1;
        }
#pragma unroll 4
        for (int k = 0; k < HID; k++) {
            float2 wp = wpL[k * 256 + t];
            F8 ha, hb;
            ha.v[0] = *(const float4*)&shA[k * GB]; ha.v[1] = *(const float4*)&shA[k * GB + 4];
            hb.v[0] = *(const float4*)&shB[k * GB]; hb.v[1] = *(const float4*)&shB[k * GB + 4];
#pragma unroll
            for (int g = 0; g < GB; g++) {
                aA[0][g] += wp.x * ha.f[g];  aA[1][g] += wp.y * ha.f[g];
                aB[0][g] += wp.x * hb.f[g];  aB[1][g] += wp.y * hb.f[g];
            }
        }
#pragma unroll
        for (int g = 0; g < GB; g++) {
            float dA0 = aA[0][g] > 0.f ? 1.f : 0.f;
            float dA1 = aA[1][g] > 0.f ? 1.f : 0.f;
            sv[t  * GB + g] *= dA0;
            sv[t1 * GB + g] *= dA1;
            g_maskB[((size_t)l * BATCH + (b0 + g)) * HID + t]  = aB[0][g] > 0.f ? 1.f : 0.f;
            g_maskB[((size_t)l * BATCH + (b0 + g)) * HID + t1] = aB[1][g] > 0.f ? 1.f : 0.f;
        }
        __syncthreads();
    }

    // ---- final: h_out = Wout h3 + bout ; h_dot = Wout v -------------------
    // remapped: s = t>>5, n0 = t&31 (lanes n-contiguous -> coalesced WoutT)
    // per-(n,s) summation order (h ascending within slice) unchanged.
    {
        float aO[2][GB], aV[2][GB];
#pragma unroll
        for (int g = 0; g < GB; g++) {
            aO[0][g] = 0.f; aV[0][g] = 0.f;
            aO[1][g] = 0.f; aV[1][g] = 0.f;
        }
        int s = t >> 5, n0 = t & 31;
        int n1 = n0 + 32;
#pragma unroll 4
        for (int hh = 0; hh < 64; hh++) {
            int h = s * 64 + hh;
            float w0 = g_WoutT[h * NDIM + n0];
            float w1 = g_WoutT[h * NDIM + n1];
            F8 ha, vv;
            ha.v[0] = *(const float4*)&shA[h * GB]; ha.v[1] = *(const float4*)&shA[h * GB + 4];
            vv.v[0] = *(const float4*)&sv [h * GB]; vv.v[1] = *(const float4*)&sv [h * GB + 4];
#pragma unroll
            for (int g = 0; g < GB; g++) {
                aO[0][g] += w0 * ha.f[g];  aO[1][g] += w1 * ha.f[g];
                aV[0][g] += w0 * vv.f[g];  aV[1][g] += w1 * vv.f[g];
            }
        }
        float* red = shB;   // reuse as scratch (4096 floats)
#pragma unroll
        for (int g = 0; g < GB; g++) {
            red[(g * 64 + n0) * 8 + s] = aO[0][g];
            red[(g * 64 + n1) * 8 + s] = aO[1][g];
        }
        __syncthreads();
        if (s == 0) {
#pragma unroll
            for (int g = 0; g < GB; g++) {
                float s0 = bout[n0], s1 = bout[n1];
                for (int ss = 0; ss < 8; ss++) {
                    s0 += red[(g * 64 + n0) * 8 + ss];
                    s1 += red[(g * 64 + n1) * 8 + ss];
                }
                out[(size_t)(b0 + g) * 192 + n0] = s0;
                out[(size_t)(b0 + g) * 192 + n1] = s1;
            }
        }
        __syncthreads();
#pragma unroll
        for (int g = 0; g < GB; g++) {
            red[(g * 64 + n0) * 8 + s] = aV[0][g];
            red[(g * 64 + n1) * 8 + s] = aV[1][g];
        }
        __syncthreads();
        if (s == 0) {
#pragma unroll
            for (int g = 0; g < GB; g++) {
                float s0 = 0.f, s1 = 0.f;
                for (int ss = 0; ss < 8; ss++) {
                    s0 += red[(g * 64 + n0) * 8 + ss];
                    s1 += red[(g * 64 + n1) * 8 + ss];
                }
                out[(size_t)(b0 + g) * 192 + 64 + n0] = s0;
                out[(size_t)(b0 + g) * 192 + 64 + n1] = s1;
            }
        }
    }
}

// ---------------- z_kernel: HMMA Jacobian chain (unchanged, proven) ----------
__device__ __forceinline__ void issue_b128(const __nv_bfloat16* __restrict__ Bg,
                                           int ns, int kc, uint32_t sB, int t) {
#pragma unroll
    for (int i = 0; i < 4; i++) {
        int flat = t + 256 * i;
        int row = flat >> 3, seg = flat & 7;
        CP16(sB + row * B_STRIDE + seg * 16,
             (const char*)(Bg + (size_t)(ns * 128 + row) * HID + kc * 64 + seg * 8));
    }
    CP_COMMIT();
}

__device__ void gemm512(const __nv_bfloat16* __restrict__ Bg,
                        const float* __restrict__ mb,
                        __nv_bfloat16* __restrict__ Ug,
                        uint32_t smu, int t)
{
    const int w = t >> 5, l = t & 31;
    const int wm = w & 3, wn = w >> 2;
    const uint32_t sA = smu + ZP_A;
    const uint32_t aRowB = (wm * 32 + (l & 15)) * A_STRIDE + ((l >> 4) << 4);
    const uint32_t bRowB = ((l & 7) + ((l >> 4) << 3)) * B_STRIDE + (((l >> 3) & 1) << 4);

#pragma unroll 1
    for (int ns = 0; ns < 4; ns++) {
        float c[2][8][4];
#pragma unroll
        for (int mt = 0; mt < 2; mt++)
#pragma unroll
            for (int nt = 0; nt < 8; nt++)
#pragma unroll
                for (int q = 0; q < 4; q++) c[mt][nt][q] = 0.f;

        issue_b128(Bg, ns, 0, smu + ZP_B, t);
        issue_b128(Bg, ns, 1, smu + ZP_B + 18432, t);

#pragma unroll
        for (int kc = 0; kc < 8; kc++) {
            if (kc == 7) { CP_WAIT(0); } else { CP_WAIT(1); }
            __syncthreads();
            uint32_t sB = smu + ZP_B + (kc & 1) * 18432;
#pragma unroll
            for (int ks = 0; ks < 4; ks++) {
                uint32_t a[2][4];
#pragma unroll
                for (int mt = 0; mt < 2; mt++)
                    ldsm4(sA + aRowB + mt * 16 * A_STRIDE + (kc * 64 + ks * 16) * 2,
                          a[mt][0], a[mt][1], a[mt][2], a[mt][3]);
                uint32_t b[8][2];
#pragma unroll
                for (int p = 0; p < 4; p++) {
                    uint32_t addr = sB + (wn * 64 + p * 16) * B_STRIDE + bRowB + ks * 32;
                    uint32_t r0, r1, r2, r3;
                    ldsm4(addr, r0, r1, r2, r3);
                    b[2 * p][0] = r0; b[2 * p][1] = r1;
                    b[2 * p + 1][0] = r2; b[2 * p + 1][1] = r3;
                }
#pragma unroll
                for (int mt = 0; mt < 2; mt++)
#pragma unroll
                    for (int nt = 0; nt < 8; nt++)
                        mma_bf16(c[mt][nt], a[mt], b[nt]);
            }
            __syncthreads();
            if (kc + 2 < 8) issue_b128(Bg, ns, kc + 2, smu + ZP_B + (kc & 1) * 18432, t);
        }

#pragma unroll
        for (int mt = 0; mt < 2; mt++) {
            int r0 = wm * 32 + mt * 16 + (l >> 2);
            const float* mk = mb + ((wm * 32 + mt * 16) >> 6) * HID;
#pragma unroll
            for (int nt = 0; nt < 8; nt++) {
                int col = ns * 128 + wn * 64 + nt * 8 + (l & 3) * 2;
                float m0 = mk[col], m1 = mk[col + 1];
                *(uint32_t*)&Ug[(size_t)r0 * HID + col] =
                    pack_bf16(c[mt][nt][0] * m0, c[mt][nt][1] * m1);
                *(uint32_t*)&Ug[(size_t)(r0 + 8) * HID + col] =
                    pack_bf16(c[mt][nt][2] * m0, c[mt][nt][3] * m1);
            }
        }
    }
    __syncthreads();

#pragma unroll
    for (int i = 0; i < 32; i++) {
        int flat = t + 256 * i;
        int row = flat >> 6, seg = flat & 63;
        CP16(sA + row * A_STRIDE + seg * 16, (const char*)(Ug + (size_t)row * HID + seg * 8));
    }
    CP_COMMIT();
    CP_WAIT(0);
    __syncthreads();
}

__device__ void gemm_final(const __nv_bfloat16* __restrict__ Bg,
                           float* __restrict__ out, int b0, uint32_t smu, int t)
{
    const int w = t >> 5, l = t & 31;
    const uint32_t sA = smu + ZP_A;
    const uint32_t aRowB = (w * 16 + (l & 15)) * A_STRIDE + ((l >> 4) << 4);
    const uint32_t bRowB = ((l & 7) + ((l >> 4) << 3)) * B_STRIDE + (((l >> 3) & 1) << 4);

    float c[8][4];
#pragma unroll
    for (int nt = 0; nt < 8; nt++)
#pragma unroll
        for (int q = 0; q < 4; q++) c[nt][q] = 0.f;

    auto issue64 = [&](int kc, uint32_t sB) {
#pragma unroll
        for (int i = 0; i < 2; i++) {
            int flat = t + 256 * i;
            int row = flat >> 3, seg = flat & 7;
            CP16(sB + row * B_STRIDE + seg * 16,
                 (const char*)(Bg + (size_t)row * HID + kc * 64 + seg * 8));
        }
        CP_COMMIT();
    };

    issue64(0, smu + ZP_B);
    issue64(1, smu + ZP_B + 18432);

#pragma unroll
    for (int kc = 0; kc < 8; kc++) {
        if (kc == 7) { CP_WAIT(0); } else { CP_WAIT(1); }
        __syncthreads();
        uint32_t sB = smu + ZP_B + (kc & 1) * 18432;
#pragma unroll
        for (int ks = 0; ks < 4; ks++) {
            uint32_t a[4];
            ldsm4(sA + aRowB + (kc * 64 + ks * 16) * 2, a[0], a[1], a[2], a[3]);
            uint32_t b[8][2];
#pragma unroll
            for (int p = 0; p < 4; p++) {
                uint32_t addr = sB + (p * 16) * B_STRIDE + bRowB + ks * 32;
                uint32_t r0, r1, r2, r3;
                ldsm4(addr, r0, r1, r2, r3);
                b[2 * p][0] = r0; b[2 * p][1] = r1;
                b[2 * p + 1][0] = r2; b[2 * p + 1][1] = r3;
            }
#pragma unroll
            for (int nt = 0; nt < 8; nt++)
                mma_bf16(c[nt], a, b[nt]);
        }
        __syncthreads();
        if (kc + 2 < 8) issue64(kc + 2, smu + ZP_B + (kc & 1) * 18432);
    }

    float s0 = 0.f, s1 = 0.f;
#pragma unroll
    for (int nt = 0; nt < 8; nt++) {
        s0 += c[nt][0] * c[nt][0] + c[nt][1] * c[nt][1];
        s1 += c[nt][2] * c[nt][2] + c[nt][3] * c[nt][3];
    }
    s0 += __shfl_xor_sync(0xFFFFFFFF, s0, 1);
    s0 += __shfl_xor_sync(0xFFFFFFFF, s0, 2);
    s1 += __shfl_xor_sync(0xFFFFFFFF, s1, 1);
    s1 += __shfl_xor_sync(0xFFFFFFFF, s1, 2);
    if ((l & 3) == 0) {
        int r0 = w * 16 + (l >> 2);
        out[(size_t)(b0 + (r0 >> 6)) * 192 + 128 + (r0 & 63)] = sqrtf(s0);
        int r1 = r0 + 8;
        out[(size_t)(b0 + (r1 >> 6)) * 192 + 128 + (r1 & 63)] = sqrtf(s1);
    }
}

__global__ __launch_bounds__(256) void z_kernel(const float* __restrict__ Wout,
                                                float* __restrict__ out)
{
    extern __shared__ char smz[];
    uint32_t smu = smem_u32(smz);
    int t = threadIdx.x;
    int b0 = blockIdx.x * 2;

    float* msk = (float*)(smz + ZP_MSK);
    for (int i = t; i < 6 * HID; i += 256) {
        int layer = i >> 10, r = i & 1023, item = r >> 9, h = r & 511;
        msk[i] = g_maskB[((size_t)layer * BATCH + b0 + item) * HID + h];
    }
    __syncthreads();

    char* sAc = smz + ZP_A;
    for (int i = t; i < 128 * 256; i += 256) {
        int m = i >> 8, p = i & 255;
        int h = p * 2;
        int item = m >> 6, n = m & 63;
        const float* d3 = msk + (4 + item) * HID;
        *(uint32_t*)(sAc + m * A_STRIDE + h * 2) =
            pack_bf16(Wout[n * HID + h] * d3[h], Wout[n * HID + h + 1] * d3[h + 1]);
    }

    __nv_bfloat16* Ug = g_U + (size_t)blockIdx.x * 128 * HID;
    gemm512(g_WT[1], msk + 2 * HID, Ug, smu, t);
    gemm512(g_WT[0], msk,           Ug, smu, t);
    gemm_final(g_G0T, out, b0, smu, t);
}

// ---------------- launch ----------------------------------------------------
extern "C" void kernel_launch(void* const* d_in, const int* in_sizes, int n_in,
                              void* d_out, int out_size)
{
    const float* x    = (const float*)d_in[0];
    const float* Win  = (const float*)d_in[1];
    const float* bin  = (const float*)d_in[2];
    const float* Wh   = (const float*)d_in[3];
    const float* bh   = (const float*)d_in[4];
    const float* Wout = (const float*)d_in[5];
    const float* bout = (const float*)d_in[6];
    float* out = (float*)d_out;

    int B = in_sizes[0] / 192;   // 4096

    const int fwd_smem = (GB * (3 * NDIM + 3 * HID)) * sizeof(float);   // 55296
    cudaFuncSetAttribute(fwd_kernel, cudaFuncAttributeMaxDynamicSharedMemorySize, fwd_smem);
    cudaFuncSetAttribute(z_kernel,   cudaFuncAttributeMaxDynamicSharedMemorySize, Z_SMEM);

    prep_g0<<<HID, NDIM>>>(Wh, Win);
    prep_wt<<<1024, 128>>>(Wh);
    prep_g0t<<<NDIM, HID>>>();
    prep_wp<<<3 * 256, 512>>>(Wh);
    prep_winp<<<256, NDIM>>>(Win);
    prep_woutt<<<HID, NDIM>>>(Wout);
    fwd_kernel<<<B / GB, 256, fwd_smem>>>(x, bin, bh, bout, out);
    z_kernel<<<B / 2, 256, Z_SMEM>>>(Wout, out);
}

// round 16
// speedup vs baseline: 6.6792x; 1.0014x over previous
#include <cuda_runtime.h>
#include <cuda_bf16.h>
#include <math.h>
#include <stdint.h>

#define BATCH 4096
#define NDIM  64
#define HID   512
#define GB    8

// ---------------- device globals (static: allocation APIs are banned) -------
__device__ float g_G0[HID * NDIM];                          // G0 = Wh0 @ Win (fp32)
__device__ float g_maskB[3 * BATCH * HID];                  // zero-branch masks
__device__ __align__(16) __nv_bfloat16 g_WT[2][HID * HID];  // Wh1^T, Wh2^T  [n][k]
__device__ __align__(16) __nv_bfloat16 g_G0T[NDIM * HID];   // G0^T [d][h]
__device__ __align__(16) __nv_bfloat16 g_U[(size_t)(BATCH / 2) * 128 * HID]; // U staging
// coalesced packed weights for fwd: [k][t] = (W[t][k], W[t+256][k])
__device__ __align__(16) float2 g_WP[3 * HID * 256];
__device__ __align__(16) float2 g_WinP[NDIM * 256];
__device__ __align__(16) float2 g_G0P[NDIM * 256];
__device__ __align__(16) float  g_WoutT[HID * NDIM];        // [h][n]

// ---------------- SMEM map for z_kernel (bytes) -----------------------------
#define ZP_MSK   0                       // 6*512 fp32 = 12288
#define ZP_A     12288                   // 128 rows * 520 bf16 = 133120
#define ZP_B     145408                  // 2 * (128 * 144B) = 36864
#define Z_SMEM   182272
#define A_STRIDE 1040                    // bytes per A row (520 bf16)
#define B_STRIDE 144                     // bytes per B row (72 bf16)

// ---------------- asm helpers ------------------------------------------------
__device__ __forceinline__ uint32_t smem_u32(const void* p) {
    uint32_t a;
    asm("{ .reg .u64 t; cvta.to.shared.u64 t, %1; cvt.u32.u64 %0, t; }" : "=r"(a) : "l"(p));
    return a;
}
#define CP16(dst, src)  asm volatile("cp.async.cg.shared.global [%0], [%1], 16;" :: "r"(dst), "l"(src))
#define CP_COMMIT()     asm volatile("cp.async.commit_group;" ::: "memory")
#define CP_WAIT(n)      asm volatile("cp.async.wait_group %0;" :: "n"(n) : "memory")

__device__ __forceinline__ void ldsm4(uint32_t addr, uint32_t& r0, uint32_t& r1,
                                      uint32_t& r2, uint32_t& r3) {
    asm volatile("ldmatrix.sync.aligned.m8n8.x4.shared.b16 {%0,%1,%2,%3}, [%4];"
        : "=r"(r0), "=r"(r1), "=r"(r2), "=r"(r3) : "r"(addr));
}
__device__ __forceinline__ void mma_bf16(float* c, const uint32_t* a, const uint32_t* b) {
    asm volatile("mma.sync.aligned.m16n8k16.row.col.f32.bf16.bf16.f32 "
        "{%0,%1,%2,%3}, {%4,%5,%6,%7}, {%8,%9}, {%0,%1,%2,%3};"
        : "+f"(c[0]), "+f"(c[1]), "+f"(c[2]), "+f"(c[3])
        : "r"(a[0]), "r"(a[1]), "r"(a[2]), "r"(a[3]), "r"(b[0]), "r"(b[1]));
}
__device__ __forceinline__ uint32_t pack_bf16(float lo, float hi) {
    uint32_t pk;
    asm("cvt.rn.bf16x2.f32 %0, %1, %2;" : "=r"(pk) : "f"(hi), "f"(lo));
    return pk;
}

// ---------------- prep kernels ----------------------------------------------
__global__ void prep_g0(const float* __restrict__ Wh, const float* __restrict__ Win) {
    int i = blockIdx.x, d = threadIdx.x;
    float acc = 0.f;
    for (int j = 0; j < HID; j++) acc += Wh[i * HID + j] * Win[j * NDIM + d];
    g_G0[i * NDIM + d] = acc;
}
__global__ void prep_wt(const float* __restrict__ Wh) {
    int li = blockIdx.x >> 9, n = blockIdx.x & 511;
    const float* base = Wh + (size_t)(li + 1) * HID * HID;
    __nv_bfloat16* dst = g_WT[li] + (size_t)n * HID;
    for (int k = threadIdx.x; k < HID; k += 128)
        dst[k] = __float2bfloat16(base[(size_t)k * HID + n]);
}
__global__ void prep_g0t() {
    int d = blockIdx.x, h = threadIdx.x;
    g_G0T[d * HID + h] = __float2bfloat16(g_G0[h * NDIM + d]);
}
// pack Wh rows (t, t+256) per k, coalesced reads
__global__ void prep_wp(const float* __restrict__ Wh) {
    int l = blockIdx.x >> 8, tt = blockIdx.x & 255;
    int k = threadIdx.x;                 // 0..511
    const float* base = Wh + (size_t)l * HID * HID;
    float w0 = base[(size_t)tt * HID + k];
    float w1 = base[(size_t)(tt + 256) * HID + k];
    g_WP[((size_t)l * HID + k) * 256 + tt] = make_float2(w0, w1);
}
__global__ void prep_winp(const float* __restrict__ Win) {
    int tt = blockIdx.x;                 // 0..255
    int d = threadIdx.x;                 // 0..63
    g_WinP[d * 256 + tt] = make_float2(Win[tt * NDIM + d], Win[(tt + 256) * NDIM + d]);
    g_G0P [d * 256 + tt] = make_float2(g_G0[tt * NDIM + d], g_G0[(tt + 256) * NDIM + d]);
}
__global__ void prep_woutt(const float* __restrict__ Wout) {
    int h = blockIdx.x, n = threadIdx.x;
    g_WoutT[h * NDIM + n] = Wout[n * HID + h];
}

// ---------------- forward: fp32 scalar, 2 rows/thread, coalesced weights -----
// Per-row summation order identical to the proven kernel -> bit-identical out.
union F8 { float4 v[2]; float f[GB]; };

__global__ __launch_bounds__(256) void fwd_kernel(
    const float* __restrict__ x,
    const float* __restrict__ bin, const float* __restrict__ bh,
    const float* __restrict__ bout,
    float* __restrict__ out)
{
    extern __shared__ float sm[];
    float* sxA = sm;                    // [64][8]
    float* sxZ = sxA + NDIM * GB;       // [64][8]
    float* sxD = sxZ + NDIM * GB;       // [64][8]
    float* shA = sxD + NDIM * GB;       // [512][8]
    float* shB = shA + HID * GB;        // [512][8]
    float* sv  = shB + HID * GB;        // [512][8]

    int t  = threadIdx.x;               // 0..255
    int t1 = t + 256;                   // second row
    int b0 = blockIdx.x * GB;

    for (int i = t; i < GB * 192; i += 256) {
        int g = i / 192, c = i % 192;
        float v = x[(b0 + g) * 192 + c];
        if (c < 64)       sxA[c * GB + g] = v;
        else if (c < 128) sxD[(c - 64) * GB + g] = v;
        else              sxZ[(c - 128) * GB + g] = v;
    }
    __syncthreads();

    // h0 (no relu) both branches + v0 = G0 @ xtdot  (2 rows per thread)
    {
        float aA[2][GB], aB[2][GB], aV[2][GB];
        float bi0 = bin[t], bi1 = bin[t1];
#pragma unroll
        for (int g = 0; g < GB; g++) {
            aA[0][g] = bi0; aB[0][g] = bi0; aV[0][g] = 0.f;
            aA[1][g] = bi1; aB[1][g] = bi1; aV[1][g] = 0.f;
        }
#pragma unroll 4
        for (int d = 0; d < NDIM; d++) {
            float2 wp = g_WinP[d * 256 + t];
            float2 gp = g_G0P [d * 256 + t];
            F8 xa, xz, xd;
            xa.v[0] = *(const float4*)&sxA[d * GB]; xa.v[1] = *(const float4*)&sxA[d * GB + 4];
            xz.v[0] = *(const float4*)&sxZ[d * GB]; xz.v[1] = *(const float4*)&sxZ[d * GB + 4];
            xd.v[0] = *(const float4*)&sxD[d * GB]; xd.v[1] = *(const float4*)&sxD[d * GB + 4];
#pragma unroll
            for (int g = 0; g < GB; g++) {
                aA[0][g] += wp.x * xa.f[g];  aA[1][g] += wp.y * xa.f[g];
                aB[0][g] += wp.x * xz.f[g];  aB[1][g] += wp.y * xz.f[g];
                aV[0][g] += gp.x * xd.f[g];  aV[1][g] += gp.y * xd.f[g];
            }
        }
#pragma unroll
        for (int g = 0; g < GB; g++) {
            shA[t  * GB + g] = aA[0][g]; shA[t1 * GB + g] = aA[1][g];
            shB[t  * GB + g] = aB[0][g]; shB[t1 * GB + g] = aB[1][g];
            sv [t  * GB + g] = aV[0][g]; sv [t1 * GB + g] = aV[1][g];
        }
    }
    __syncthreads();

#pragma unroll 1
    for (int l = 0; l < 3; l++) {
        const float2* wpL = g_WP + (size_t)l * HID * 256;
        float bias0 = bh[l * HID + t], bias1 = bh[l * HID + t1];

        // ---- pass 1: h_{l+1} = relu(W h_l + b); v = W v (layers 1,2) ----
        float aA[2][GB], aB[2][GB], aV[2][GB];
#pragma unroll
        for (int g = 0; g < GB; g++) {
            aA[0][g] = bias0; aB[0][g] = bias0; aV[0][g] = 0.f;
            aA[1][g] = bias1; aB[1][g] = bias1; aV[1][g] = 0.f;
        }
#pragma unroll 4
        for (int k = 0; k < HID; k++) {
            float2 wp = wpL[k * 256 + t];
            F8 ha, hb, vv;
            ha.v[0] = *(const float4*)&shA[k * GB]; ha.v[1] = *(const float4*)&shA[k * GB + 4];
            hb.v[0] = *(const float4*)&shB[k * GB]; hb.v[1] = *(const float4*)&shB[k * GB + 4];
            if (l > 0) {
                vv.v[0] = *(const float4*)&sv[k * GB]; vv.v[1] = *(const float4*)&sv[k * GB + 4];
            }
#pragma unroll
            for (int g = 0; g < GB; g++) {
                aA[0][g] += wp.x * ha.f[g];  aA[1][g] += wp.y * ha.f[g];
                aB[0][g] += wp.x * hb.f[g];  aB[1][g] += wp.y * hb.f[g];
                if (l > 0) { aV[0][g] += wp.x * vv.f[g]; aV[1][g] += wp.y * vv.f[g]; }
            }
        }
        __syncthreads();   // all reads done before overwriting
#pragma unroll
        for (int g = 0; g < GB; g++) {
            shA[t  * GB + g] = fmaxf(aA[0][g], 0.f);
            shA[t1 * GB + g] = fmaxf(aA[1][g], 0.f);
            shB[t  * GB + g] = fmaxf(aB[0][g], 0.f);
            shB[t1 * GB + g] = fmaxf(aB[1][g], 0.f);
            if (l > 0) { sv[t * GB + g] = aV[0][g]; sv[t1 * GB + g] = aV[1][g]; }
        }
        __syncthreads();

        // ---- pass 2: delta^{(l)} = (W h_{l+1} + b > 0)  (bug-faithful mask)
#pragma unroll
        for (int g = 0; g < GB; g++) {
            aA[0][g] = bias0; aB[0][g] = bias0;
            aA[1][g] = bias1; aB[1][g] = bias1;
        }
#pragma unroll 4
        for (int k = 0; k < HID; k++) {
            float2 wp = wpL[k * 256 + t];
            F8 ha, hb;
            ha.v[0] = *(const float4*)&shA[k * GB]; ha.v[1] = *(const float4*)&shA[k * GB + 4];
            hb.v[0] = *(const float4*)&shB[k * GB]; hb.v[1] = *(const float4*)&shB[k * GB + 4];
#pragma unroll
            for (int g = 0; g < GB; g++) {
                aA[0][g] += wp.x * ha.f[g];  aA[1][g] += wp.y * ha.f[g];
                aB[0][g] += wp.x * hb.f[g];  aB[1][g] += wp.y * hb.f[g];
            }
        }
#pragma unroll
        for (int g = 0; g < GB; g++) {
            float dA0 = aA[0][g] > 0.f ? 1.f : 0.f;
            float dA1 = aA[1][g] > 0.f ? 1.f : 0.f;
            sv[t  * GB + g] *= dA0;
            sv[t1 * GB + g] *= dA1;
            g_maskB[((size_t)l * BATCH + (b0 + g)) * HID + t]  = aB[0][g] > 0.f ? 1.f : 0.f;
            g_maskB[((size_t)l * BATCH + (b0 + g)) * HID + t1] = aB[1][g] > 0.f ? 1.f : 0.f;
        }
        __syncthreads();
    }

    // ---- final: h_out = Wout h3 + bout ; h_dot = Wout v -------------------
    // remapped: s = t>>5, n0 = t&31 (lanes n-contiguous -> coalesced WoutT)
    // per-(n,s) summation order (h ascending within slice) unchanged.
    {
        float aO[2][GB], aV[2][GB];
#pragma unroll
        for (int g = 0; g < GB; g++) {
            aO[0][g] = 0.f; aV[0][g] = 0.f;
            aO[1][g] = 0.f; aV[1][g] = 0.f;
        }
        int s = t >> 5, n0 = t & 31;
        int n1 = n0 + 32;
#pragma unroll 4
        for (int hh = 0; hh < 64; hh++) {
            int h = s * 64 + hh;
            float w0 = g_WoutT[h * NDIM + n0];
            float w1 = g_WoutT[h * NDIM + n1];
            F8 ha, vv;
            ha.v[0] = *(const float4*)&shA[h * GB]; ha.v[1] = *(const float4*)&shA[h * GB + 4];
            vv.v[0] = *(const float4*)&sv [h * GB]; vv.v[1] = *(const float4*)&sv [h * GB + 4];
#pragma unroll
            for (int g = 0; g < GB; g++) {
                aO[0][g] += w0 * ha.f[g];  aO[1][g] += w1 * ha.f[g];
                aV[0][g] += w0 * vv.f[g];  aV[1][g] += w1 * vv.f[g];
            }
        }
        float* red = shB;   // reuse as scratch (4096 floats)
#pragma unroll
        for (int g = 0; g < GB; g++) {
            red[(g * 64 + n0) * 8 + s] = aO[0][g];
            red[(g * 64 + n1) * 8 + s] = aO[1][g];
        }
        __syncthreads();
        if (s == 0) {
#pragma unroll
            for (int g = 0; g < GB; g++) {
                float s0 = bout[n0], s1 = bout[n1];
                for (int ss = 0; ss < 8; ss++) {
                    s0 += red[(g * 64 + n0) * 8 + ss];
                    s1 += red[(g * 64 + n1) * 8 + ss];
                }
                out[(size_t)(b0 + g) * 192 + n0] = s0;
                out[(size_t)(b0 + g) * 192 + n1] = s1;
            }
        }
        __syncthreads();
#pragma unroll
        for (int g = 0; g < GB; g++) {
            red[(g * 64 + n0) * 8 + s] = aV[0][g];
            red[(g * 64 + n1) * 8 + s] = aV[1][g];
        }
        __syncthreads();
        if (s == 0) {
#pragma unroll
            for (int g = 0; g < GB; g++) {
                float s0 = 0.f, s1 = 0.f;
                for (int ss = 0; ss < 8; ss++) {
                    s0 += red[(g * 64 + n0) * 8 + ss];
                    s1 += red[(g * 64 + n1) * 8 + ss];
                }
                out[(size_t)(b0 + g) * 192 + 64 + n0] = s0;
                out[(size_t)(b0 + g) * 192 + 64 + n1] = s1;
            }
        }
    }
}

// ---------------- z_kernel: HMMA Jacobian chain (unchanged, proven) ----------
__device__ __forceinline__ void issue_b128(const __nv_bfloat16* __restrict__ Bg,
                                           int ns, int kc, uint32_t sB, int t) {
#pragma unroll
    for (int i = 0; i < 4; i++) {
        int flat = t + 256 * i;
        int row = flat >> 3, seg = flat & 7;
        CP16(sB + row * B_STRIDE + seg * 16,
             (const char*)(Bg + (size_t)(ns * 128 + row) * HID + kc * 64 + seg * 8));
    }
    CP_COMMIT();
}

__device__ void gemm512(const __nv_bfloat16* __restrict__ Bg,
                        const float* __restrict__ mb,
                        __nv_bfloat16* __restrict__ Ug,
                        uint32_t smu, int t)
{
    const int w = t >> 5, l = t & 31;
    const int wm = w & 3, wn = w >> 2;
    const uint32_t sA = smu + ZP_A;
    const uint32_t aRowB = (wm * 32 + (l & 15)) * A_STRIDE + ((l >> 4) << 4);
    const uint32_t bRowB = ((l & 7) + ((l >> 4) << 3)) * B_STRIDE + (((l >> 3) & 1) << 4);

#pragma unroll 1
    for (int ns = 0; ns < 4; ns++) {
        float c[2][8][4];
#pragma unroll
        for (int mt = 0; mt < 2; mt++)
#pragma unroll
            for (int nt = 0; nt < 8; nt++)
#pragma unroll
                for (int q = 0; q < 4; q++) c[mt][nt][q] = 0.f;

        issue_b128(Bg, ns, 0, smu + ZP_B, t);
        issue_b128(Bg, ns, 1, smu + ZP_B + 18432, t);

#pragma unroll
        for (int kc = 0; kc < 8; kc++) {
            if (kc == 7) { CP_WAIT(0); } else { CP_WAIT(1); }
            __syncthreads();
            uint32_t sB = smu + ZP_B + (kc & 1) * 18432;
#pragma unroll
            for (int ks = 0; ks < 4; ks++) {
                uint32_t a[2][4];
#pragma unroll
                for (int mt = 0; mt < 2; mt++)
                    ldsm4(sA + aRowB + mt * 16 * A_STRIDE + (kc * 64 + ks * 16) * 2,
                          a[mt][0], a[mt][1], a[mt][2], a[mt][3]);
                uint32_t b[8][2];
#pragma unroll
                for (int p = 0; p < 4; p++) {
                    uint32_t addr = sB + (wn * 64 + p * 16) * B_STRIDE + bRowB + ks * 32;
                    uint32_t r0, r1, r2, r3;
                    ldsm4(addr, r0, r1, r2, r3);
                    b[2 * p][0] = r0; b[2 * p][1] = r1;
                    b[2 * p + 1][0] = r2; b[2 * p + 1][1] = r3;
                }
#pragma unroll
                for (int mt = 0; mt < 2; mt++)
#pragma unroll
                    for (int nt = 0; nt < 8; nt++)
                        mma_bf16(c[mt][nt], a[mt], b[nt]);
            }
            __syncthreads();
            if (kc + 2 < 8) issue_b128(Bg, ns, kc + 2, smu + ZP_B + (kc & 1) * 18432, t);
        }

#pragma unroll
        for (int mt = 0; mt < 2; mt++) {
            int r0 = wm * 32 + mt * 16 + (l >> 2);
            const float* mk = mb + ((wm * 32 + mt * 16) >> 6) * HID;
#pragma unroll
            for (int nt = 0; nt < 8; nt++) {
                int col = ns * 128 + wn * 64 + nt * 8 + (l & 3) * 2;
                float m0 = mk[col], m1 = mk[col + 1];
                *(uint32_t*)&Ug[(size_t)r0 * HID + col] =
                    pack_bf16(c[mt][nt][0] * m0, c[mt][nt][1] * m1);
                *(uint32_t*)&Ug[(size_t)(r0 + 8) * HID + col] =
                    pack_bf16(c[mt][nt][2] * m0, c[mt][nt][3] * m1);
            }
        }
    }
    __syncthreads();

#pragma unroll
    for (int i = 0; i < 32; i++) {
        int flat = t + 256 * i;
        int row = flat >> 6, seg = flat & 63;
        CP16(sA + row * A_STRIDE + seg * 16, (const char*)(Ug + (size_t)row * HID + seg * 8));
    }
    CP_COMMIT();
    CP_WAIT(0);
    __syncthreads();
}

__device__ void gemm_final(const __nv_bfloat16* __restrict__ Bg,
                           float* __restrict__ out, int b0, uint32_t smu, int t)
{
    const int w = t >> 5, l = t & 31;
    const uint32_t sA = smu + ZP_A;
    const uint32_t aRowB = (w * 16 + (l & 15)) * A_STRIDE + ((l >> 4) << 4);
    const uint32_t bRowB = ((l & 7) + ((l >> 4) << 3)) * B_STRIDE + (((l >> 3) & 1) << 4);

    float c[8][4];
#pragma unroll
    for (int nt = 0; nt < 8; nt++)
#pragma unroll
        for (int q = 0; q < 4; q++) c[nt][q] = 0.f;

    auto issue64 = [&](int kc, uint32_t sB) {
#pragma unroll
        for (int i = 0; i < 2; i++) {
            int flat = t + 256 * i;
            int row = flat >> 3, seg = flat & 7;
            CP16(sB + row * B_STRIDE + seg * 16,
                 (const char*)(Bg + (size_t)row * HID + kc * 64 + seg * 8));
        }
        CP_COMMIT();
    };

    issue64(0, smu + ZP_B);
    issue64(1, smu + ZP_B + 18432);

#pragma unroll
    for (int kc = 0; kc < 8; kc++) {
        if (kc == 7) { CP_WAIT(0); } else { CP_WAIT(1); }
        __syncthreads();
        uint32_t sB = smu + ZP_B + (kc & 1) * 18432;
#pragma unroll
        for (int ks = 0; ks < 4; ks++) {
            uint32_t a[4];
            ldsm4(sA + aRowB + (kc * 64 + ks * 16) * 2, a[0], a[1], a[2], a[3]);
            uint32_t b[8][2];
#pragma unroll
            for (int p = 0; p < 4; p++) {
                uint32_t addr = sB + (p * 16) * B_STRIDE + bRowB + ks * 32;
                uint32_t r0, r1, r2, r3;
                ldsm4(addr, r0, r1, r2, r3);
                b[2 * p][0] = r0; b[2 * p][1] = r1;
                b[2 * p + 1][0] = r2; b[2 * p + 1][1] = r3;
            }
#pragma unroll
            for (int nt = 0; nt < 8; nt++)
                mma_bf16(c[nt], a, b[nt]);
        }
        __syncthreads();
        if (kc + 2 < 8) issue64(kc + 2, smu + ZP_B + (kc & 1) * 18432);
    }

    float s0 = 0.f, s1 = 0.f;
#pragma unroll
    for (int nt = 0; nt < 8; nt++) {
        s0 += c[nt][0] * c[nt][0] + c[nt][1] * c[nt][1];
        s1 += c[nt][2] * c[nt][2] + c[nt][3] * c[nt][3];
    }
    s0 += __shfl_xor_sync(0xFFFFFFFF, s0, 1);
    s0 += __shfl_xor_sync(0xFFFFFFFF, s0, 2);
    s1 += __shfl_xor_sync(0xFFFFFFFF, s1, 1);
    s1 += __shfl_xor_sync(0xFFFFFFFF, s1, 2);
    if ((l & 3) == 0) {
        int r0 = w * 16 + (l >> 2);
        out[(size_t)(b0 + (r0 >> 6)) * 192 + 128 + (r0 & 63)] = sqrtf(s0);
        int r1 = r0 + 8;
        out[(size_t)(b0 + (r1 >> 6)) * 192 + 128 + (r1 & 63)] = sqrtf(s1);
    }
}

__global__ __launch_bounds__(256) void z_kernel(const float* __restrict__ Wout,
                                                float* __restrict__ out)
{
    extern __shared__ char smz[];
    uint32_t smu = smem_u32(smz);
    int t = threadIdx.x;
    int b0 = blockIdx.x * 2;

    float* msk = (float*)(smz + ZP_MSK);
    for (int i = t; i < 6 * HID; i += 256) {
        int layer = i >> 10, r = i & 1023, item = r >> 9, h = r & 511;
        msk[i] = g_maskB[((size_t)layer * BATCH + b0 + item) * HID + h];
    }
    __syncthreads();

    char* sAc = smz + ZP_A;
    for (int i = t; i < 128 * 256; i += 256) {
        int m = i >> 8, p = i & 255;
        int h = p * 2;
        int item = m >> 6, n = m & 63;
        const float* d3 = msk + (4 + item) * HID;
        *(uint32_t*)(sAc + m * A_STRIDE + h * 2) =
            pack_bf16(Wout[n * HID + h] * d3[h], Wout[n * HID + h + 1] * d3[h + 1]);
    }

    __nv_bfloat16* Ug = g_U + (size_t)blockIdx.x * 128 * HID;
    gemm512(g_WT[1], msk + 2 * HID, Ug, smu, t);
    gemm512(g_WT[0], msk,           Ug, smu, t);
    gemm_final(g_G0T, out, b0, smu, t);
}

// ---------------- launch ----------------------------------------------------
extern "C" void kernel_launch(void* const* d_in, const int* in_sizes, int n_in,
                              void* d_out, int out_size)
{
    const float* x    = (const float*)d_in[0];
    const float* Win  = (const float*)d_in[1];
    const float* bin  = (const float*)d_in[2];
    const float* Wh   = (const float*)d_in[3];
    const float* bh   = (const float*)d_in[4];
    const float* Wout = (const float*)d_in[5];
    const float* bout = (const float*)d_in[6];
    float* out = (float*)d_out;

    int B = in_sizes[0] / 192;   // 4096

    const int fwd_smem = (GB * (3 * NDIM + 3 * HID)) * sizeof(float);   // 55296
    cudaFuncSetAttribute(fwd_kernel, cudaFuncAttributeMaxDynamicSharedMemorySize, fwd_smem);
    cudaFuncSetAttribute(z_kernel,   cudaFuncAttributeMaxDynamicSharedMemorySize, Z_SMEM);

    prep_g0<<<HID, NDIM>>>(Wh, Win);
    prep_wt<<<1024, 128>>>(Wh);
    prep_g0t<<<NDIM, HID>>>();
    prep_wp<<<3 * 256, 512>>>(Wh);
    prep_winp<<<256, NDIM>>>(Win);
    prep_woutt<<<HID, NDIM>>>(Wout);
    fwd_kernel<<<B / GB, 256, fwd_smem>>>(x, bin, bh, bout, out);
    z_kernel<<<B / 2, 256, Z_SMEM>>>(Wout, out);
}